// round 10
// baseline (speedup 1.0000x reference)
#include <cuda_runtime.h>
#include <math.h>

#define EDGES 65536
#define GRID  2048
#define EPB   (EDGES / GRID)   // 32 edges per block
#define W3J_TOTAL 1875
#define NZ_MAX 1875
#define OUT_ALL_OFF ((size_t)EDGES * 9 * 128)   // 75497472
#define NSPLIT 29              // 128 - 99 spare thread tasks
#define NZT 10                 // register-resident nz entries per thread

// ---- key tables: (la, lb, lo) for the 23 distinct W3J tensors, in weight-path order ----
__constant__ int KEY_LA[23]  = {0,1,2,3, 0,1,1,2,2,3, 0,1,1,2,2,3,3, 0,1,2,2,3,3};
__constant__ int KEY_LB[23]  = {0,1,2,3, 1,0,2,1,3,2, 2,1,3,0,2,1,3, 3,2,1,3,0,2};
__constant__ int KEY_LO[23]  = {0,0,0,0, 1,1,1,1,1,1, 2,2,2,2,2,2,2, 3,3,3,3,3,3};
__constant__ int W3J_OFF[23] = {0,1,10,35, 84,93,102,147,192,297,
                                402,427,472,577,602,727,832,
                                1077,1126,1231,1336,1581,1630};

__constant__ float c_factf[11]  = {1.f,1.f,2.f,6.f,24.f,120.f,720.f,5040.f,40320.f,362880.f,3628800.f};
__constant__ float c_rfactf[11] = {1.0f, 1.0f, 0.5f, 1.0f/6.0f, 1.0f/24.0f, 1.0f/120.0f, 1.0f/720.0f,
                                   1.0f/5040.0f, 1.0f/40320.0f, 1.0f/362880.0f, 1.0f/3628800.0f};

__device__ float g_w3j[W3J_TOTAL];
__device__ float2 g_nz[NZ_MAX];
// per-thread task tables (built by compress kernel)
__device__ int g_toff[128];
__device__ int g_tcnt[128];
__device__ int g_tdst[128];    // z-index in padded layout, or -1
__device__ int g_tpair[128];   // 1 = add shfl-down(1) partner before writing
__device__ int g_total;

// ================= init: fp32 Wigner-3j tensors =================
struct F2 { float re, im; };
__device__ __forceinline__ F2 cmul(F2 a, F2 b) {
    return F2{a.re * b.re - a.im * b.im, a.re * b.im + a.im * b.re};
}
__device__ __forceinline__ F2 cconj(F2 a) { return F2{a.re, -a.im}; }
__device__ __forceinline__ F2 cscale(F2 a, float s) { return F2{a.re * s, a.im * s}; }

__device__ float su2_cg(int j1, int m1, int j2, int m2, int j3, int m3) {
    if (m3 != m1 + m2) return 0.0f;
    float pref = sqrtf((2.0f * j3 + 1.0f) * c_factf[j3 + j1 - j2] * c_factf[j3 - j1 + j2] *
                       c_factf[j1 + j2 - j3] * c_rfactf[j1 + j2 + j3 + 1]);
    pref *= sqrtf(c_factf[j3 + m3] * c_factf[j3 - m3] * c_factf[j1 - m1] * c_factf[j1 + m1] *
                  c_factf[j2 - m2] * c_factf[j2 + m2]);
    int kmin = max(0, max(j2 - j3 - m1, j1 - j3 + m2));
    int kmax = min(j1 + j2 - j3, min(j1 - m1, j2 + m2));
    float s = 0.0f;
    for (int k = kmin; k <= kmax; k++) {
        float term = c_rfactf[k] * c_rfactf[j1 + j2 - j3 - k] * c_rfactf[j1 - m1 - k] *
                     c_rfactf[j2 + m2 - k] * c_rfactf[j3 - j2 + m1 + k] * c_rfactf[j3 - j1 - m2 + k];
        s += (k & 1) ? -term : term;
    }
    return pref * s;
}

__device__ __forceinline__ F2 negi_pow(int l) {
    switch (l & 3) {
        case 0: return F2{1.0f, 0.0f};
        case 1: return F2{0.0f, -1.0f};
        case 2: return F2{-1.0f, 0.0f};
        default: return F2{0.0f, 1.0f};
    }
}

__device__ int q_col_entries(int l, int c, int* rows, F2* vals) {
    F2 pref = negi_pow(l);
    const float s = 0.70710678f;
    int mu = c - l;
    if (mu == 0) { rows[0] = l; vals[0] = pref; return 1; }
    if (mu > 0) {
        rows[0] = l - mu; vals[0] = cscale(pref, s);
        float sgn = (mu & 1) ? -1.0f : 1.0f;
        rows[1] = l + mu; vals[1] = cscale(pref, sgn * s);
        return 2;
    }
    int a = -mu;
    rows[0] = l - a; vals[0] = cmul(pref, F2{0.0f, -s});
    float sgn = (a & 1) ? -1.0f : 1.0f;
    rows[1] = l + a; vals[1] = cmul(pref, F2{0.0f, sgn * s});
    return 2;
}

__device__ int q_row_entries(int l, int r, int* cols, F2* vals) {
    F2 pref = negi_pow(l);
    const float s = 0.70710678f;
    int mu = r - l;
    if (mu == 0) { cols[0] = l; vals[0] = pref; return 1; }
    if (mu < 0) {
        int a = -mu;
        cols[0] = l + a; vals[0] = cscale(pref, s);
        cols[1] = l - a; vals[1] = cmul(pref, F2{0.0f, -s});
        return 2;
    }
    float sgn = (mu & 1) ? -1.0f : 1.0f;
    cols[0] = l + mu; vals[0] = cscale(pref, sgn * s);
    cols[1] = l - mu; vals[1] = cmul(pref, F2{0.0f, sgn * s});
    return 2;
}

__global__ void w3j_init_kernel() {
    __shared__ float sC[343];
    __shared__ float sCr[245];
    __shared__ float sred[256];
    int key = blockIdx.x;
    int la = KEY_LA[key], lb = KEY_LB[key], lo = KEY_LO[key];
    int na = 2 * la + 1, nb = 2 * lb + 1, no = 2 * lo + 1;
    int n = na * nb * no;
    int t = threadIdx.x;

    for (int idx = t; idx < n; idx += blockDim.x) {
        int i = idx / (nb * no);
        int rem = idx % (nb * no);
        int k = rem / no;
        int m = rem % no;
        int m1 = i - la, m2 = k - lb, m3 = m - lo;
        sC[idx] = (m3 == m1 + m2) ? su2_cg(la, m1, lb, m2, lo, m3) : 0.0f;
    }
    __syncthreads();

    float local_sq = 0.0f;
    for (int idx = t; idx < n; idx += blockDim.x) {
        int ja = idx / (nb * no);
        int rem = idx % (nb * no);
        int jb = rem / no;
        int jn = rem % no;
        int r1[2]; F2 v1[2]; int n1 = q_col_entries(la, ja, r1, v1);
        int r2[2]; F2 v2[2]; int n2 = q_col_entries(lb, jb, r2, v2);
        int c3[2]; F2 v3[2]; int n3 = q_row_entries(lo, jn, c3, v3);
        F2 acc{0.0f, 0.0f};
        for (int a = 0; a < n1; a++)
            for (int b = 0; b < n2; b++)
                for (int c = 0; c < n3; c++) {
                    F2 q = cmul(cmul(v1[a], v2[b]), cconj(v3[c]));
                    float cv = sC[(r1[a] * nb + r2[b]) * no + c3[c]];
                    acc.re += q.re * cv;
                    acc.im += q.im * cv;
                }
        sCr[idx] = acc.re;
        local_sq += acc.re * acc.re;
    }
    sred[t] = local_sq;
    __syncthreads();
    for (int s = 128; s > 0; s >>= 1) {
        if (t < s) sred[t] += sred[t + s];
        __syncthreads();
    }
    float inv = rsqrtf(sred[0]);
    for (int idx = t; idx < n; idx += blockDim.x)
        g_w3j[W3J_OFF[key] + idx] = sCr[idx] * inv;
}

// slot (0..98) -> (key, k-within-output)
__device__ __forceinline__ void slot_decode(int t, int& key, int& k) {
    if (t < 4) { key = t; k = 0; }
    else if (t < 22) { int q = t - 4; key = 4 + q / 3; k = q % 3; }
    else if (t < 57) { int q = t - 22; key = 10 + q / 5; k = q % 5; }
    else { int q = t - 57; key = 17 + q / 7; k = q % 7; }
}

// slot -> index within padded z layout (sZ[104])
__device__ __forceinline__ int zmap(int slot) {
    return slot + (slot >= 22 ? 2 : 0) + (slot >= 57 ? 1 : 0);
}

// ========== compress: nonzero lists + load-balanced 128-thread task table ==========
__global__ void w3j_compress_kernel() {
    __shared__ int scnt[99];
    __shared__ int soff[99];
    int t = threadIdx.x;
    int key = 0, k = 0;
    bool valid = (t < 99);
    if (valid) slot_decode(t, key, k);
    int la = KEY_LA[key], lb = KEY_LB[key], lo = KEY_LO[key];
    int na = 2 * la + 1, nb = 2 * lb + 1, no = 2 * lo + 1;
    int woff = W3J_OFF[key];
    int cnt = 0;
    if (valid) {
        for (int i = 0; i < na; i++)
            for (int j = 0; j < nb; j++)
                if (fabsf(g_w3j[woff + (i * nb + j) * no + k]) > 1e-10f) cnt++;
        scnt[t] = cnt;
    }
    __syncthreads();
    if (t == 0) {
        int acc = 0;
        for (int i = 0; i < 99; i++) { soff[i] = acc; acc += scnt[i]; }
        g_total = acc;
    }
    __syncthreads();
    if (valid) {
        int w = soff[t];
        for (int i = 0; i < na; i++)
            for (int j = 0; j < nb; j++) {
                float c = g_w3j[woff + (i * nb + j) * no + k];
                if (fabsf(c) > 1e-10f) {
                    int pidx = (la * la + i) * 16 + (lb * lb + j);  // index into 16x16 product table
                    g_nz[w++] = make_float2(c, __int_as_float(pidx));
                }
            }
    }
    __syncthreads();
    // rank slots by nnz (descending, ties by index); split top NSPLIT across thread pairs
    if (valid) {
        int rank = 0;
        for (int j = 0; j < 99; j++)
            if (scnt[j] > cnt || (scnt[j] == cnt && j < t)) rank++;
        int off = soff[t];
        int dst = zmap(t);
        if (rank < NSPLIT) {
            int p0 = 2 * rank;
            int c1 = (cnt + 1) >> 1;
            g_toff[p0] = off;          g_tcnt[p0] = c1;       g_tdst[p0] = dst;  g_tpair[p0] = 1;
            g_toff[p0 + 1] = off + c1; g_tcnt[p0 + 1] = cnt - c1; g_tdst[p0 + 1] = -1; g_tpair[p0 + 1] = 0;
        } else {
            int p = 2 * NSPLIT + (rank - NSPLIT);   // 58..127
            g_toff[p] = off; g_tcnt[p] = cnt; g_tdst[p] = dst; g_tpair[p] = 0;
        }
    }
}

// ================= main kernel =================
__device__ __forceinline__ float fsig(float v) { return 1.0f / (1.0f + __expf(-v)); }

__global__ void __launch_bounds__(128)
cg_main_kernel(const float* __restrict__ x, const float* __restrict__ y,
               const float* __restrict__ wcg, const float* __restrict__ bcg,
               const float* __restrict__ wall, const float* __restrict__ ball,
               float* __restrict__ out) {
    __shared__ float sProd[4][256];                 // per-warp product tables
    __shared__ __align__(16) float sZ[2][104];      // ping-pong z buffers
    __shared__ float sWall[35];
    __shared__ float sBall[4];

    int t = threadIdx.x;
    int w = t >> 5, lane = t & 31;
    if (t < 35) sWall[t] = wall[t];
    if (t < 4) sBall[t] = ball[t];

    // per-thread phase-1 task, nz stream preloaded into registers
    int toff = g_toff[t], tcnt = g_tcnt[t], tdst = g_tdst[t], tpair = g_tpair[t];
    float rc[NZT];
    int   ri[NZT];
#pragma unroll
    for (int n = 0; n < NZT; n++) {
        if (n < tcnt) {
            float2 e = g_nz[toff + n];
            rc[n] = e.x;
            ri[n] = __float_as_int(e.y);
        } else {
            rc[n] = 0.0f;
            ri[n] = 0;
        }
    }

    // per-channel weights hoisted to registers (fixed across edges)
    float w00 = wcg[t], w01 = wcg[128 + t], w02 = wcg[256 + t], w03 = wcg[384 + t];
    float a0w = wcg[512 + t], a1w = wcg[768 + t], a2w = wcg[1024 + t], a3w = wcg[1280 + t];
    float c0w = wcg[640 + t], c1w = wcg[896 + t], c2w = wcg[1152 + t], c3w = wcg[1408 + t];
    float uw0 = wcg[1536 + t], uw1 = wcg[1664 + t], uw2 = wcg[1792 + t];
    float uw3 = wcg[1920 + t], uw4 = wcg[2048 + t], uw5 = wcg[2176 + t];
    float vw0 = wcg[2304 + t], vw1 = wcg[2432 + t], vw2 = wcg[2560 + t], vw3 = wcg[2688 + t];
    float vw4 = wcg[2816 + t], vw5 = wcg[2944 + t], vw6 = wcg[3072 + t];
    float b0 = bcg[t], b1 = bcg[128 + t], b2 = bcg[256 + t];

    int e0 = blockIdx.x * EPB;
    // every warp holds the edge's x/y in lanes 0-31 (x in 0-15, y in 16-31)
    float pre = (lane < 16) ? x[(size_t)e0 * 16 + lane] : y[(size_t)e0 * 16 + (lane - 16)];

    // order the cooperative sWall/sBall loads before any phase-2 reads
    __syncthreads();

    for (int ei = 0; ei < EPB; ++ei) {
        int e = e0 + ei;
        // each warp builds its own 16x16 product table (no block barrier needed)
        float v = pre;
#pragma unroll
        for (int r = 0; r < 8; r++) {
            int p = r * 32 + lane;
            sProd[w][p] = __shfl_sync(0xffffffffu, v, p >> 4) *
                          __shfl_sync(0xffffffffu, v, 16 + (p & 15));
        }
        if (ei + 1 < EPB) {
            int en = e + 1;
            pre = (lane < 16) ? x[(size_t)en * 16 + lane] : y[(size_t)en * 16 + (lane - 16)];
        }
        __syncwarp();

        // ---- phase 1: register-stream sparse z, fully unrolled ----
        float* zb = sZ[ei & 1];
        {
            const float* P = sProd[w];
            float acc = 0.0f;
#pragma unroll
            for (int n = 0; n < NZT; n++)
                acc = fmaf(rc[n], P[ri[n]], acc);
            // safety tail for any thread whose task exceeds NZT (normally none)
            for (int n = NZT; n < tcnt; n++) {
                float2 ent = g_nz[toff + n];
                acc = fmaf(ent.x, P[__float_as_int(ent.y)], acc);
            }
            float oth = __shfl_down_sync(0xffffffffu, acc, 1);
            if (tpair) acc += oth;
            if (tdst >= 0) zb[tdst] = acc;
        }
        __syncthreads();   // the only per-edge block barrier

        // ---- phase 2: per-channel outputs (t = channel) ----
        const float* Z = zb;
        float4 z0 = *(const float4*)Z;
        float v0 = fmaf(z0.x, w00, fmaf(z0.y, w01, fmaf(z0.z, w02, z0.w * w03)));
        v0 = 0.5f * v0 + b0;
        float scv = v0 * fsig(v0);
        float g0 = fmaf(z0.x, a0w, fmaf(z0.y, a1w, fmaf(z0.z, a2w, z0.w * a3w)));
        g0 = fsig(0.5f * g0 + b1);
        float g1 = fmaf(z0.x, c0w, fmaf(z0.y, c1w, fmaf(z0.z, c2w, z0.w * c3w)));
        g1 = fsig(0.5f * g1 + b2);

        // entry 2 (lo=1): u_k = sum_p Z[4+3p+k]*uw_p (18 values at Z+4)
        float u0, u1, u2;
        {
            float4 v4;
            v4 = *(const float4*)(Z + 4);
            u0 = v4.x * uw0; u1 = v4.y * uw0; u2 = v4.z * uw0; u0 = fmaf(v4.w, uw1, u0);
            v4 = *(const float4*)(Z + 8);
            u1 = fmaf(v4.x, uw1, u1); u2 = fmaf(v4.y, uw1, u2);
            u0 = fmaf(v4.z, uw2, u0); u1 = fmaf(v4.w, uw2, u1);
            v4 = *(const float4*)(Z + 12);
            u2 = fmaf(v4.x, uw2, u2); u0 = fmaf(v4.y, uw3, u0);
            u1 = fmaf(v4.z, uw3, u1); u2 = fmaf(v4.w, uw3, u2);
            v4 = *(const float4*)(Z + 16);
            u0 = fmaf(v4.x, uw4, u0); u1 = fmaf(v4.y, uw4, u1);
            u2 = fmaf(v4.z, uw4, u2); u0 = fmaf(v4.w, uw5, u0);
            float2 v2 = *(const float2*)(Z + 20);
            u1 = fmaf(v2.x, uw5, u1); u2 = fmaf(v2.y, uw5, u2);
        }
        // entry 3 (lo=2): q_k = sum_p Z[24+5p+k]*vw_p (35 values at Z+24)
        float q0, q1, q2, q3, q4;
        {
            float4 v4;
            v4 = *(const float4*)(Z + 24);
            q0 = v4.x * vw0; q1 = v4.y * vw0; q2 = v4.z * vw0; q3 = v4.w * vw0;
            v4 = *(const float4*)(Z + 28);
            q4 = v4.x * vw0; q0 = fmaf(v4.y, vw1, q0); q1 = fmaf(v4.z, vw1, q1); q2 = fmaf(v4.w, vw1, q2);
            v4 = *(const float4*)(Z + 32);
            q3 = fmaf(v4.x, vw1, q3); q4 = fmaf(v4.y, vw1, q4); q0 = fmaf(v4.z, vw2, q0); q1 = fmaf(v4.w, vw2, q1);
            v4 = *(const float4*)(Z + 36);
            q2 = fmaf(v4.x, vw2, q2); q3 = fmaf(v4.y, vw2, q3); q4 = fmaf(v4.z, vw2, q4); q0 = fmaf(v4.w, vw3, q0);
            v4 = *(const float4*)(Z + 40);
            q1 = fmaf(v4.x, vw3, q1); q2 = fmaf(v4.y, vw3, q2); q3 = fmaf(v4.z, vw3, q3); q4 = fmaf(v4.w, vw3, q4);
            v4 = *(const float4*)(Z + 44);
            q0 = fmaf(v4.x, vw4, q0); q1 = fmaf(v4.y, vw4, q1); q2 = fmaf(v4.z, vw4, q2); q3 = fmaf(v4.w, vw4, q3);
            v4 = *(const float4*)(Z + 48);
            q4 = fmaf(v4.x, vw4, q4); q0 = fmaf(v4.y, vw5, q0); q1 = fmaf(v4.z, vw5, q1); q2 = fmaf(v4.w, vw5, q2);
            v4 = *(const float4*)(Z + 52);
            q3 = fmaf(v4.x, vw5, q3); q4 = fmaf(v4.y, vw5, q4); q0 = fmaf(v4.z, vw6, q0); q1 = fmaf(v4.w, vw6, q1);
            v4 = *(const float4*)(Z + 56);   // Z[59] is padding (lane discarded)
            q2 = fmaf(v4.x, vw6, q2); q3 = fmaf(v4.y, vw6, q3); q4 = fmaf(v4.z, vw6, q4);
        }

        const float S1 = 0.70710678118654752f;   // sqrt(3/6)
        const float S2 = 0.84515425472851657f;   // sqrt(5/7)
        size_t base = ((size_t)e * 9) * 128 + t;
        out[base] = scv;
        float gg = S1 * g0;
        out[base + 128] = u0 * gg;
        out[base + 256] = u1 * gg;
        out[base + 384] = u2 * gg;
        float hh = S2 * g1;
        out[base + 512] = q0 * hh;
        out[base + 640] = q1 * hh;
        out[base + 768] = q2 * hh;
        out[base + 896] = q3 * hh;
        out[base + 1024] = q4 * hh;

        // ---- "all" branch: 16 outputs ----
        if (t < 16) {
            float* oa = out + OUT_ALL_OFF + (size_t)e * 16;
            if (t == 0) {
                float vv = 0.5f * (z0.x * sWall[0] + z0.y * sWall[1] + z0.z * sWall[2] + z0.w * sWall[3]) + sBall[0];
                oa[0] = vv * fsig(vv);
            } else if (t < 4) {
                int k = t - 1;
                float g = fsig(0.5f * (z0.x * sWall[4] + z0.y * sWall[7] + z0.z * sWall[10] + z0.w * sWall[13]) + sBall[1]);
                float u = 0.f;
#pragma unroll
                for (int p = 0; p < 6; p++) u += Z[4 + 3 * p + k] * sWall[16 + p];
                oa[t] = 0.70710678118654752f * u * g;
            } else if (t < 9) {
                int k = t - 4;
                float g = fsig(0.5f * (z0.x * sWall[5] + z0.y * sWall[8] + z0.z * sWall[11] + z0.w * sWall[14]) + sBall[2]);
                float u = 0.f;
#pragma unroll
                for (int p = 0; p < 7; p++) u += Z[24 + 5 * p + k] * sWall[22 + p];
                oa[t] = 0.84515425472851657f * u * g;
            } else {
                int k = t - 9;
                float g = fsig(0.5f * (z0.x * sWall[6] + z0.y * sWall[9] + z0.z * sWall[12] + z0.w * sWall[15]) + sBall[3]);
                float u = 0.f;
#pragma unroll
                for (int p = 0; p < 6; p++) u += Z[60 + 7 * p + k] * sWall[29 + p];
                oa[t] = 1.08012344973464367f * u * g;   // sqrt(7/6)
            }
        }
        // no trailing barrier: ping-pong sZ + the per-edge barrier give the
        // needed ordering (reaching edge ei+2's phase-1 writes requires passing
        // edge ei+1's barrier, which is after all edge-ei phase-2 reads).
    }
}

extern "C" void kernel_launch(void* const* d_in, const int* in_sizes, int n_in,
                              void* d_out, int out_size) {
    const float* x    = (const float*)d_in[0];
    const float* y    = (const float*)d_in[1];
    const float* wcg  = (const float*)d_in[2];
    const float* bcg  = (const float*)d_in[3];
    const float* wall = (const float*)d_in[4];
    const float* ball = (const float*)d_in[5];
    float* out = (float*)d_out;

    w3j_init_kernel<<<23, 256>>>();
    w3j_compress_kernel<<<1, 128>>>();
    cg_main_kernel<<<GRID, 128>>>(x, y, wcg, bcg, wall, ball, out);
}

// round 11
// speedup vs baseline: 1.1067x; 1.1067x over previous
#include <cuda_runtime.h>
#include <math.h>

#define EDGES 65536
#define GRID  4096
#define EPB   (EDGES / GRID)   // 16 edges per block
#define W3J_TOTAL 1875
#define NZ_MAX 1875
#define OUT_ALL_OFF ((size_t)EDGES * 9 * 128)   // 75497472
#define NSPLIT 29              // 128 - 99 spare thread tasks

// ---- key tables: (la, lb, lo) for the 23 distinct W3J tensors, in weight-path order ----
__constant__ int KEY_LA[23]  = {0,1,2,3, 0,1,1,2,2,3, 0,1,1,2,2,3,3, 0,1,2,2,3,3};
__constant__ int KEY_LB[23]  = {0,1,2,3, 1,0,2,1,3,2, 2,1,3,0,2,1,3, 3,2,1,3,0,2};
__constant__ int KEY_LO[23]  = {0,0,0,0, 1,1,1,1,1,1, 2,2,2,2,2,2,2, 3,3,3,3,3,3};
__constant__ int W3J_OFF[23] = {0,1,10,35, 84,93,102,147,192,297,
                                402,427,472,577,602,727,832,
                                1077,1126,1231,1336,1581,1630};

__constant__ float c_factf[11]  = {1.f,1.f,2.f,6.f,24.f,120.f,720.f,5040.f,40320.f,362880.f,3628800.f};
__constant__ float c_rfactf[11] = {1.0f, 1.0f, 0.5f, 1.0f/6.0f, 1.0f/24.0f, 1.0f/120.0f, 1.0f/720.0f,
                                   1.0f/5040.0f, 1.0f/40320.0f, 1.0f/362880.0f, 1.0f/3628800.0f};

__device__ float g_w3j[W3J_TOTAL];
__device__ float2 g_nz[NZ_MAX];
// per-thread task tables (built by compress kernel)
__device__ int g_toff[128];
__device__ int g_tcnt[128];
__device__ int g_tdst[128];    // z-index in padded layout, or -1
__device__ int g_tpair[128];   // 1 = add shfl-down(1) partner before writing
__device__ int g_total;

// ================= init: fp32 Wigner-3j tensors =================
struct F2 { float re, im; };
__device__ __forceinline__ F2 cmul(F2 a, F2 b) {
    return F2{a.re * b.re - a.im * b.im, a.re * b.im + a.im * b.re};
}
__device__ __forceinline__ F2 cconj(F2 a) { return F2{a.re, -a.im}; }
__device__ __forceinline__ F2 cscale(F2 a, float s) { return F2{a.re * s, a.im * s}; }

__device__ float su2_cg(int j1, int m1, int j2, int m2, int j3, int m3) {
    if (m3 != m1 + m2) return 0.0f;
    float pref = sqrtf((2.0f * j3 + 1.0f) * c_factf[j3 + j1 - j2] * c_factf[j3 - j1 + j2] *
                       c_factf[j1 + j2 - j3] * c_rfactf[j1 + j2 + j3 + 1]);
    pref *= sqrtf(c_factf[j3 + m3] * c_factf[j3 - m3] * c_factf[j1 - m1] * c_factf[j1 + m1] *
                  c_factf[j2 - m2] * c_factf[j2 + m2]);
    int kmin = max(0, max(j2 - j3 - m1, j1 - j3 + m2));
    int kmax = min(j1 + j2 - j3, min(j1 - m1, j2 + m2));
    float s = 0.0f;
    for (int k = kmin; k <= kmax; k++) {
        float term = c_rfactf[k] * c_rfactf[j1 + j2 - j3 - k] * c_rfactf[j1 - m1 - k] *
                     c_rfactf[j2 + m2 - k] * c_rfactf[j3 - j2 + m1 + k] * c_rfactf[j3 - j1 - m2 + k];
        s += (k & 1) ? -term : term;
    }
    return pref * s;
}

__device__ __forceinline__ F2 negi_pow(int l) {
    switch (l & 3) {
        case 0: return F2{1.0f, 0.0f};
        case 1: return F2{0.0f, -1.0f};
        case 2: return F2{-1.0f, 0.0f};
        default: return F2{0.0f, 1.0f};
    }
}

__device__ int q_col_entries(int l, int c, int* rows, F2* vals) {
    F2 pref = negi_pow(l);
    const float s = 0.70710678f;
    int mu = c - l;
    if (mu == 0) { rows[0] = l; vals[0] = pref; return 1; }
    if (mu > 0) {
        rows[0] = l - mu; vals[0] = cscale(pref, s);
        float sgn = (mu & 1) ? -1.0f : 1.0f;
        rows[1] = l + mu; vals[1] = cscale(pref, sgn * s);
        return 2;
    }
    int a = -mu;
    rows[0] = l - a; vals[0] = cmul(pref, F2{0.0f, -s});
    float sgn = (a & 1) ? -1.0f : 1.0f;
    rows[1] = l + a; vals[1] = cmul(pref, F2{0.0f, sgn * s});
    return 2;
}

__device__ int q_row_entries(int l, int r, int* cols, F2* vals) {
    F2 pref = negi_pow(l);
    const float s = 0.70710678f;
    int mu = r - l;
    if (mu == 0) { cols[0] = l; vals[0] = pref; return 1; }
    if (mu < 0) {
        int a = -mu;
        cols[0] = l + a; vals[0] = cscale(pref, s);
        cols[1] = l - a; vals[1] = cmul(pref, F2{0.0f, -s});
        return 2;
    }
    float sgn = (mu & 1) ? -1.0f : 1.0f;
    cols[0] = l + mu; vals[0] = cscale(pref, sgn * s);
    cols[1] = l - mu; vals[1] = cmul(pref, F2{0.0f, sgn * s});
    return 2;
}

__global__ void w3j_init_kernel() {
    __shared__ float sC[343];
    __shared__ float sCr[245];
    __shared__ float sred[8];
    int key = blockIdx.x;
    int la = KEY_LA[key], lb = KEY_LB[key], lo = KEY_LO[key];
    int na = 2 * la + 1, nb = 2 * lb + 1, no = 2 * lo + 1;
    int n = na * nb * no;
    int t = threadIdx.x;

    for (int idx = t; idx < n; idx += blockDim.x) {
        int i = idx / (nb * no);
        int rem = idx % (nb * no);
        int k = rem / no;
        int m = rem % no;
        int m1 = i - la, m2 = k - lb, m3 = m - lo;
        sC[idx] = (m3 == m1 + m2) ? su2_cg(la, m1, lb, m2, lo, m3) : 0.0f;
    }
    __syncthreads();

    float local_sq = 0.0f;
    for (int idx = t; idx < n; idx += blockDim.x) {
        int ja = idx / (nb * no);
        int rem = idx % (nb * no);
        int jb = rem / no;
        int jn = rem % no;
        int r1[2]; F2 v1[2]; int n1 = q_col_entries(la, ja, r1, v1);
        int r2[2]; F2 v2[2]; int n2 = q_col_entries(lb, jb, r2, v2);
        int c3[2]; F2 v3[2]; int n3 = q_row_entries(lo, jn, c3, v3);
        F2 acc{0.0f, 0.0f};
        for (int a = 0; a < n1; a++)
            for (int b = 0; b < n2; b++)
                for (int c = 0; c < n3; c++) {
                    F2 q = cmul(cmul(v1[a], v2[b]), cconj(v3[c]));
                    float cv = sC[(r1[a] * nb + r2[b]) * no + c3[c]];
                    acc.re += q.re * cv;
                    acc.im += q.im * cv;
                }
        sCr[idx] = acc.re;
        local_sq += acc.re * acc.re;
    }
    // warp-shuffle reduction, then tiny cross-warp pass
    for (int o = 16; o > 0; o >>= 1)
        local_sq += __shfl_down_sync(0xffffffffu, local_sq, o);
    if ((t & 31) == 0) sred[t >> 5] = local_sq;
    __syncthreads();
    float tot = sred[0] + sred[1] + sred[2] + sred[3] +
                sred[4] + sred[5] + sred[6] + sred[7];
    float inv = rsqrtf(tot);
    for (int idx = t; idx < n; idx += blockDim.x)
        g_w3j[W3J_OFF[key] + idx] = sCr[idx] * inv;
}

// slot (0..98) -> (key, k-within-output)
__device__ __forceinline__ void slot_decode(int t, int& key, int& k) {
    if (t < 4) { key = t; k = 0; }
    else if (t < 22) { int q = t - 4; key = 4 + q / 3; k = q % 3; }
    else if (t < 57) { int q = t - 22; key = 10 + q / 5; k = q % 5; }
    else { int q = t - 57; key = 17 + q / 7; k = q % 7; }
}

// slot -> index within padded z layout (sZ[104])
__device__ __forceinline__ int zmap(int slot) {
    return slot + (slot >= 22 ? 2 : 0) + (slot >= 57 ? 1 : 0);
}

// ========== compress: nonzero lists + load-balanced 128-thread task table ==========
__global__ void w3j_compress_kernel() {
    __shared__ int scnt[99];
    __shared__ int soff[99];
    int t = threadIdx.x;
    int key = 0, k = 0;
    bool valid = (t < 99);
    if (valid) slot_decode(t, key, k);
    int la = KEY_LA[key], lb = KEY_LB[key], lo = KEY_LO[key];
    int na = 2 * la + 1, nb = 2 * lb + 1, no = 2 * lo + 1;
    int woff = W3J_OFF[key];
    int cnt = 0;
    if (valid) {
        for (int i = 0; i < na; i++)
            for (int j = 0; j < nb; j++)
                if (fabsf(g_w3j[woff + (i * nb + j) * no + k]) > 1e-10f) cnt++;
        scnt[t] = cnt;
    }
    __syncthreads();
    if (t == 0) {
        int acc = 0;
        for (int i = 0; i < 99; i++) { soff[i] = acc; acc += scnt[i]; }
        g_total = acc;
    }
    __syncthreads();
    if (valid) {
        int w = soff[t];
        for (int i = 0; i < na; i++)
            for (int j = 0; j < nb; j++) {
                float c = g_w3j[woff + (i * nb + j) * no + k];
                if (fabsf(c) > 1e-10f) {
                    int pidx = (la * la + i) * 16 + (lb * lb + j);  // index into 16x16 product table
                    g_nz[w++] = make_float2(c, __int_as_float(pidx));
                }
            }
    }
    __syncthreads();
    // rank slots by nnz (descending, ties by index); split top NSPLIT across thread pairs
    if (valid) {
        int rank = 0;
        for (int j = 0; j < 99; j++)
            if (scnt[j] > cnt || (scnt[j] == cnt && j < t)) rank++;
        int off = soff[t];
        int dst = zmap(t);
        if (rank < NSPLIT) {
            int p0 = 2 * rank;
            int c1 = (cnt + 1) >> 1;
            g_toff[p0] = off;          g_tcnt[p0] = c1;       g_tdst[p0] = dst;  g_tpair[p0] = 1;
            g_toff[p0 + 1] = off + c1; g_tcnt[p0 + 1] = cnt - c1; g_tdst[p0 + 1] = -1; g_tpair[p0 + 1] = 0;
        } else {
            int p = 2 * NSPLIT + (rank - NSPLIT);   // 58..127
            g_toff[p] = off; g_tcnt[p] = cnt; g_tdst[p] = dst; g_tpair[p] = 0;
        }
    }
}

// ================= main kernel =================
__device__ __forceinline__ float fsig(float v) { return 1.0f / (1.0f + __expf(-v)); }

__global__ void __launch_bounds__(128, 7)
cg_main_kernel(const float* __restrict__ x, const float* __restrict__ y,
               const float* __restrict__ wcg, const float* __restrict__ bcg,
               const float* __restrict__ wall, const float* __restrict__ ball,
               float* __restrict__ out) {
    __shared__ float2 snz[NZ_MAX];
    __shared__ float sProd[4][256];                 // per-warp product tables
    __shared__ __align__(16) float sZ[2][104];      // ping-pong z buffers
    __shared__ float sWall[35];
    __shared__ float sBall[4];

    int t = threadIdx.x;
    int w = t >> 5, lane = t & 31;
    int total = g_total;
    for (int i = t; i < total; i += 128) snz[i] = g_nz[i];
    if (t < 35) sWall[t] = wall[t];
    if (t < 4) sBall[t] = ball[t];

    // per-thread phase-1 task
    int toff = g_toff[t], tcnt = g_tcnt[t], tdst = g_tdst[t], tpair = g_tpair[t];

    // per-channel weights hoisted to registers (fixed across edges)
    float w00 = wcg[t], w01 = wcg[128 + t], w02 = wcg[256 + t], w03 = wcg[384 + t];
    float a0w = wcg[512 + t], a1w = wcg[768 + t], a2w = wcg[1024 + t], a3w = wcg[1280 + t];
    float c0w = wcg[640 + t], c1w = wcg[896 + t], c2w = wcg[1152 + t], c3w = wcg[1408 + t];
    float uw0 = wcg[1536 + t], uw1 = wcg[1664 + t], uw2 = wcg[1792 + t];
    float uw3 = wcg[1920 + t], uw4 = wcg[2048 + t], uw5 = wcg[2176 + t];
    float vw0 = wcg[2304 + t], vw1 = wcg[2432 + t], vw2 = wcg[2560 + t], vw3 = wcg[2688 + t];
    float vw4 = wcg[2816 + t], vw5 = wcg[2944 + t], vw6 = wcg[3072 + t];
    float b0 = bcg[t], b1 = bcg[128 + t], b2 = bcg[256 + t];

    int e0 = blockIdx.x * EPB;
    // every warp holds the edge's x/y in lanes 0-31 (x in 0-15, y in 16-31)
    float pre = (lane < 16) ? x[(size_t)e0 * 16 + lane] : y[(size_t)e0 * 16 + (lane - 16)];

    // order the cooperative snz/sWall/sBall loads before any thread's phase-1 reads
    __syncthreads();

    for (int ei = 0; ei < EPB; ++ei) {
        int e = e0 + ei;
        // each warp builds its own 16x16 product table (no block barrier needed)
        float v = pre;
#pragma unroll
        for (int r = 0; r < 8; r++) {
            int p = r * 32 + lane;
            sProd[w][p] = __shfl_sync(0xffffffffu, v, p >> 4) *
                          __shfl_sync(0xffffffffu, v, 16 + (p & 15));
        }
        if (ei + 1 < EPB) {
            int en = e + 1;
            pre = (lane < 16) ? x[(size_t)en * 16 + lane] : y[(size_t)en * 16 + (lane - 16)];
        }
        __syncwarp();

        // ---- phase 1: balanced sparse z tasks, warp-local reads ----
        float* zb = sZ[ei & 1];
        {
            const float* P = sProd[w];
            float acc = 0.0f;
#pragma unroll 4
            for (int n = 0; n < tcnt; n++) {
                float2 ent = snz[toff + n];
                acc = fmaf(ent.x, P[__float_as_int(ent.y)], acc);
            }
            float oth = __shfl_down_sync(0xffffffffu, acc, 1);
            if (tpair) acc += oth;
            if (tdst >= 0) zb[tdst] = acc;
        }
        __syncthreads();   // the only per-edge block barrier

        // ---- phase 2: per-channel outputs (t = channel) ----
        const float* Z = zb;
        float4 z0 = *(const float4*)Z;
        float v0 = fmaf(z0.x, w00, fmaf(z0.y, w01, fmaf(z0.z, w02, z0.w * w03)));
        v0 = 0.5f * v0 + b0;
        float scv = v0 * fsig(v0);
        float g0 = fmaf(z0.x, a0w, fmaf(z0.y, a1w, fmaf(z0.z, a2w, z0.w * a3w)));
        g0 = fsig(0.5f * g0 + b1);
        float g1 = fmaf(z0.x, c0w, fmaf(z0.y, c1w, fmaf(z0.z, c2w, z0.w * c3w)));
        g1 = fsig(0.5f * g1 + b2);

        // entry 2 (lo=1): u_k = sum_p Z[4+3p+k]*uw_p (18 values at Z+4)
        float u0, u1, u2;
        {
            float4 v4;
            v4 = *(const float4*)(Z + 4);
            u0 = v4.x * uw0; u1 = v4.y * uw0; u2 = v4.z * uw0; u0 = fmaf(v4.w, uw1, u0);
            v4 = *(const float4*)(Z + 8);
            u1 = fmaf(v4.x, uw1, u1); u2 = fmaf(v4.y, uw1, u2);
            u0 = fmaf(v4.z, uw2, u0); u1 = fmaf(v4.w, uw2, u1);
            v4 = *(const float4*)(Z + 12);
            u2 = fmaf(v4.x, uw2, u2); u0 = fmaf(v4.y, uw3, u0);
            u1 = fmaf(v4.z, uw3, u1); u2 = fmaf(v4.w, uw3, u2);
            v4 = *(const float4*)(Z + 16);
            u0 = fmaf(v4.x, uw4, u0); u1 = fmaf(v4.y, uw4, u1);
            u2 = fmaf(v4.z, uw4, u2); u0 = fmaf(v4.w, uw5, u0);
            float2 v2 = *(const float2*)(Z + 20);
            u1 = fmaf(v2.x, uw5, u1); u2 = fmaf(v2.y, uw5, u2);
        }
        // entry 3 (lo=2): q_k = sum_p Z[24+5p+k]*vw_p (35 values at Z+24)
        float q0, q1, q2, q3, q4;
        {
            float4 v4;
            v4 = *(const float4*)(Z + 24);
            q0 = v4.x * vw0; q1 = v4.y * vw0; q2 = v4.z * vw0; q3 = v4.w * vw0;
            v4 = *(const float4*)(Z + 28);
            q4 = v4.x * vw0; q0 = fmaf(v4.y, vw1, q0); q1 = fmaf(v4.z, vw1, q1); q2 = fmaf(v4.w, vw1, q2);
            v4 = *(const float4*)(Z + 32);
            q3 = fmaf(v4.x, vw1, q3); q4 = fmaf(v4.y, vw1, q4); q0 = fmaf(v4.z, vw2, q0); q1 = fmaf(v4.w, vw2, q1);
            v4 = *(const float4*)(Z + 36);
            q2 = fmaf(v4.x, vw2, q2); q3 = fmaf(v4.y, vw2, q3); q4 = fmaf(v4.z, vw2, q4); q0 = fmaf(v4.w, vw3, q0);
            v4 = *(const float4*)(Z + 40);
            q1 = fmaf(v4.x, vw3, q1); q2 = fmaf(v4.y, vw3, q2); q3 = fmaf(v4.z, vw3, q3); q4 = fmaf(v4.w, vw3, q4);
            v4 = *(const float4*)(Z + 44);
            q0 = fmaf(v4.x, vw4, q0); q1 = fmaf(v4.y, vw4, q1); q2 = fmaf(v4.z, vw4, q2); q3 = fmaf(v4.w, vw4, q3);
            v4 = *(const float4*)(Z + 48);
            q4 = fmaf(v4.x, vw4, q4); q0 = fmaf(v4.y, vw5, q0); q1 = fmaf(v4.z, vw5, q1); q2 = fmaf(v4.w, vw5, q2);
            v4 = *(const float4*)(Z + 52);
            q3 = fmaf(v4.x, vw5, q3); q4 = fmaf(v4.y, vw5, q4); q0 = fmaf(v4.z, vw6, q0); q1 = fmaf(v4.w, vw6, q1);
            v4 = *(const float4*)(Z + 56);   // Z[59] is padding (lane discarded)
            q2 = fmaf(v4.x, vw6, q2); q3 = fmaf(v4.y, vw6, q3); q4 = fmaf(v4.z, vw6, q4);
        }

        const float S1 = 0.70710678118654752f;   // sqrt(3/6)
        const float S2 = 0.84515425472851657f;   // sqrt(5/7)
        size_t base = ((size_t)e * 9) * 128 + t;
        out[base] = scv;
        float gg = S1 * g0;
        out[base + 128] = u0 * gg;
        out[base + 256] = u1 * gg;
        out[base + 384] = u2 * gg;
        float hh = S2 * g1;
        out[base + 512] = q0 * hh;
        out[base + 640] = q1 * hh;
        out[base + 768] = q2 * hh;
        out[base + 896] = q3 * hh;
        out[base + 1024] = q4 * hh;

        // ---- "all" branch: 16 outputs ----
        if (t < 16) {
            float* oa = out + OUT_ALL_OFF + (size_t)e * 16;
            if (t == 0) {
                float vv = 0.5f * (z0.x * sWall[0] + z0.y * sWall[1] + z0.z * sWall[2] + z0.w * sWall[3]) + sBall[0];
                oa[0] = vv * fsig(vv);
            } else if (t < 4) {
                int k = t - 1;
                float g = fsig(0.5f * (z0.x * sWall[4] + z0.y * sWall[7] + z0.z * sWall[10] + z0.w * sWall[13]) + sBall[1]);
                float u = 0.f;
#pragma unroll
                for (int p = 0; p < 6; p++) u += Z[4 + 3 * p + k] * sWall[16 + p];
                oa[t] = 0.70710678118654752f * u * g;
            } else if (t < 9) {
                int k = t - 4;
                float g = fsig(0.5f * (z0.x * sWall[5] + z0.y * sWall[8] + z0.z * sWall[11] + z0.w * sWall[14]) + sBall[2]);
                float u = 0.f;
#pragma unroll
                for (int p = 0; p < 7; p++) u += Z[24 + 5 * p + k] * sWall[22 + p];
                oa[t] = 0.84515425472851657f * u * g;
            } else {
                int k = t - 9;
                float g = fsig(0.5f * (z0.x * sWall[6] + z0.y * sWall[9] + z0.z * sWall[12] + z0.w * sWall[15]) + sBall[3]);
                float u = 0.f;
#pragma unroll
                for (int p = 0; p < 6; p++) u += Z[60 + 7 * p + k] * sWall[29 + p];
                oa[t] = 1.08012344973464367f * u * g;   // sqrt(7/6)
            }
        }
        // no trailing barrier: ping-pong sZ + the per-edge barrier give the
        // needed ordering (reaching edge ei+2's phase-1 writes requires passing
        // edge ei+1's barrier, which is after all edge-ei phase-2 reads).
    }
}

extern "C" void kernel_launch(void* const* d_in, const int* in_sizes, int n_in,
                              void* d_out, int out_size) {
    const float* x    = (const float*)d_in[0];
    const float* y    = (const float*)d_in[1];
    const float* wcg  = (const float*)d_in[2];
    const float* bcg  = (const float*)d_in[3];
    const float* wall = (const float*)d_in[4];
    const float* ball = (const float*)d_in[5];
    float* out = (float*)d_out;

    w3j_init_kernel<<<23, 256>>>();
    w3j_compress_kernel<<<1, 128>>>();
    cg_main_kernel<<<GRID, 128>>>(x, y, wcg, bcg, wall, ball, out);
}

// round 13
// speedup vs baseline: 1.2176x; 1.1002x over previous
#include <cuda_runtime.h>
#include <math.h>

#define EDGES 65536
#define GRID  4096
#define EPB   (EDGES / GRID)   // 16 edges per block
#define PAIRS (EPB / 2)        // 8 edge-pairs per block
#define W3J_TOTAL 1875
#define NZ_MAX 1875
#define OUT_ALL_OFF ((size_t)EDGES * 9 * 128)   // 75497472
#define NSPLIT 29              // 128 - 99 spare thread tasks

// ---- key tables: (la, lb, lo) for the 23 distinct W3J tensors, in weight-path order ----
__constant__ int KEY_LA[23]  = {0,1,2,3, 0,1,1,2,2,3, 0,1,1,2,2,3,3, 0,1,2,2,3,3};
__constant__ int KEY_LB[23]  = {0,1,2,3, 1,0,2,1,3,2, 2,1,3,0,2,1,3, 3,2,1,3,0,2};
__constant__ int KEY_LO[23]  = {0,0,0,0, 1,1,1,1,1,1, 2,2,2,2,2,2,2, 3,3,3,3,3,3};
__constant__ int W3J_OFF[23] = {0,1,10,35, 84,93,102,147,192,297,
                                402,427,472,577,602,727,832,
                                1077,1126,1231,1336,1581,1630};

__constant__ float c_factf[11]  = {1.f,1.f,2.f,6.f,24.f,120.f,720.f,5040.f,40320.f,362880.f,3628800.f};
__constant__ float c_rfactf[11] = {1.0f, 1.0f, 0.5f, 1.0f/6.0f, 1.0f/24.0f, 1.0f/120.0f, 1.0f/720.0f,
                                   1.0f/5040.0f, 1.0f/40320.0f, 1.0f/362880.0f, 1.0f/3628800.0f};

__device__ float g_w3j[W3J_TOTAL];
__device__ float2 g_nz[NZ_MAX];
// per-thread task tables (built by compress kernel)
__device__ int g_toff[128];
__device__ int g_tcnt[128];
__device__ int g_tdst[128];    // z-index in padded layout, or -1
__device__ int g_tpair[128];   // 1 = add shfl-down(1) partner before writing
__device__ int g_total;

// ================= init: fp32 Wigner-3j tensors =================
struct F2 { float re, im; };
__device__ __forceinline__ F2 cmul(F2 a, F2 b) {
    return F2{a.re * b.re - a.im * b.im, a.re * b.im + a.im * b.re};
}
__device__ __forceinline__ F2 cconj(F2 a) { return F2{a.re, -a.im}; }
__device__ __forceinline__ F2 cscale(F2 a, float s) { return F2{a.re * s, a.im * s}; }

__device__ float su2_cg(int j1, int m1, int j2, int m2, int j3, int m3) {
    if (m3 != m1 + m2) return 0.0f;
    float pref = sqrtf((2.0f * j3 + 1.0f) * c_factf[j3 + j1 - j2] * c_factf[j3 - j1 + j2] *
                       c_factf[j1 + j2 - j3] * c_rfactf[j1 + j2 + j3 + 1]);
    pref *= sqrtf(c_factf[j3 + m3] * c_factf[j3 - m3] * c_factf[j1 - m1] * c_factf[j1 + m1] *
                  c_factf[j2 - m2] * c_factf[j2 + m2]);
    int kmin = max(0, max(j2 - j3 - m1, j1 - j3 + m2));
    int kmax = min(j1 + j2 - j3, min(j1 - m1, j2 + m2));
    float s = 0.0f;
    for (int k = kmin; k <= kmax; k++) {
        float term = c_rfactf[k] * c_rfactf[j1 + j2 - j3 - k] * c_rfactf[j1 - m1 - k] *
                     c_rfactf[j2 + m2 - k] * c_rfactf[j3 - j2 + m1 + k] * c_rfactf[j3 - j1 - m2 + k];
        s += (k & 1) ? -term : term;
    }
    return pref * s;
}

__device__ __forceinline__ F2 negi_pow(int l) {
    switch (l & 3) {
        case 0: return F2{1.0f, 0.0f};
        case 1: return F2{0.0f, -1.0f};
        case 2: return F2{-1.0f, 0.0f};
        default: return F2{0.0f, 1.0f};
    }
}

__device__ int q_col_entries(int l, int c, int* rows, F2* vals) {
    F2 pref = negi_pow(l);
    const float s = 0.70710678f;
    int mu = c - l;
    if (mu == 0) { rows[0] = l; vals[0] = pref; return 1; }
    if (mu > 0) {
        rows[0] = l - mu; vals[0] = cscale(pref, s);
        float sgn = (mu & 1) ? -1.0f : 1.0f;
        rows[1] = l + mu; vals[1] = cscale(pref, sgn * s);
        return 2;
    }
    int a = -mu;
    rows[0] = l - a; vals[0] = cmul(pref, F2{0.0f, -s});
    float sgn = (a & 1) ? -1.0f : 1.0f;
    rows[1] = l + a; vals[1] = cmul(pref, F2{0.0f, sgn * s});
    return 2;
}

__device__ int q_row_entries(int l, int r, int* cols, F2* vals) {
    F2 pref = negi_pow(l);
    const float s = 0.70710678f;
    int mu = r - l;
    if (mu == 0) { cols[0] = l; vals[0] = pref; return 1; }
    if (mu < 0) {
        int a = -mu;
        cols[0] = l + a; vals[0] = cscale(pref, s);
        cols[1] = l - a; vals[1] = cmul(pref, F2{0.0f, -s});
        return 2;
    }
    float sgn = (mu & 1) ? -1.0f : 1.0f;
    cols[0] = l + mu; vals[0] = cscale(pref, sgn * s);
    cols[1] = l - mu; vals[1] = cmul(pref, F2{0.0f, sgn * s});
    return 2;
}

__global__ void w3j_init_kernel() {
    __shared__ float sC[343];
    __shared__ float sCr[245];
    __shared__ float sred[8];
    int key = blockIdx.x;
    int la = KEY_LA[key], lb = KEY_LB[key], lo = KEY_LO[key];
    int na = 2 * la + 1, nb = 2 * lb + 1, no = 2 * lo + 1;
    int n = na * nb * no;
    int t = threadIdx.x;

    for (int idx = t; idx < n; idx += blockDim.x) {
        int i = idx / (nb * no);
        int rem = idx % (nb * no);
        int k = rem / no;
        int m = rem % no;
        int m1 = i - la, m2 = k - lb, m3 = m - lo;
        sC[idx] = (m3 == m1 + m2) ? su2_cg(la, m1, lb, m2, lo, m3) : 0.0f;
    }
    __syncthreads();

    float local_sq = 0.0f;
    for (int idx = t; idx < n; idx += blockDim.x) {
        int ja = idx / (nb * no);
        int rem = idx % (nb * no);
        int jb = rem / no;
        int jn = rem % no;
        int r1[2]; F2 v1[2]; int n1 = q_col_entries(la, ja, r1, v1);
        int r2[2]; F2 v2[2]; int n2 = q_col_entries(lb, jb, r2, v2);
        int c3[2]; F2 v3[2]; int n3 = q_row_entries(lo, jn, c3, v3);
        F2 acc{0.0f, 0.0f};
        for (int a = 0; a < n1; a++)
            for (int b = 0; b < n2; b++)
                for (int c = 0; c < n3; c++) {
                    F2 q = cmul(cmul(v1[a], v2[b]), cconj(v3[c]));
                    float cv = sC[(r1[a] * nb + r2[b]) * no + c3[c]];
                    acc.re += q.re * cv;
                    acc.im += q.im * cv;
                }
        sCr[idx] = acc.re;
        local_sq += acc.re * acc.re;
    }
    for (int o = 16; o > 0; o >>= 1)
        local_sq += __shfl_down_sync(0xffffffffu, local_sq, o);
    if ((t & 31) == 0) sred[t >> 5] = local_sq;
    __syncthreads();
    float tot = sred[0] + sred[1] + sred[2] + sred[3] +
                sred[4] + sred[5] + sred[6] + sred[7];
    float inv = rsqrtf(tot);
    for (int idx = t; idx < n; idx += blockDim.x)
        g_w3j[W3J_OFF[key] + idx] = sCr[idx] * inv;
}

// slot (0..98) -> (key, k-within-output)
__device__ __forceinline__ void slot_decode(int t, int& key, int& k) {
    if (t < 4) { key = t; k = 0; }
    else if (t < 22) { int q = t - 4; key = 4 + q / 3; k = q % 3; }
    else if (t < 57) { int q = t - 22; key = 10 + q / 5; k = q % 5; }
    else { int q = t - 57; key = 17 + q / 7; k = q % 7; }
}

// slot -> index within padded z layout (sZ[104])
__device__ __forceinline__ int zmap(int slot) {
    return slot + (slot >= 22 ? 2 : 0) + (slot >= 57 ? 1 : 0);
}

// ========== compress: nonzero lists + load-balanced 128-thread task table ==========
__global__ void w3j_compress_kernel() {
    __shared__ int scnt[99];
    __shared__ int soff[99];
    int t = threadIdx.x;
    int key = 0, k = 0;
    bool valid = (t < 99);
    if (valid) slot_decode(t, key, k);
    int la = KEY_LA[key], lb = KEY_LB[key], lo = KEY_LO[key];
    int na = 2 * la + 1, nb = 2 * lb + 1, no = 2 * lo + 1;
    int woff = W3J_OFF[key];
    int cnt = 0;
    if (valid) {
        for (int i = 0; i < na; i++)
            for (int j = 0; j < nb; j++)
                if (fabsf(g_w3j[woff + (i * nb + j) * no + k]) > 1e-10f) cnt++;
        scnt[t] = cnt;
    }
    __syncthreads();
    if (t == 0) {
        int acc = 0;
        for (int i = 0; i < 99; i++) { soff[i] = acc; acc += scnt[i]; }
        g_total = acc;
    }
    __syncthreads();
    if (valid) {
        int w = soff[t];
        for (int i = 0; i < na; i++)
            for (int j = 0; j < nb; j++) {
                float c = g_w3j[woff + (i * nb + j) * no + k];
                if (fabsf(c) > 1e-10f) {
                    int pidx = (la * la + i) * 16 + (lb * lb + j);  // index into 16x16 product table
                    g_nz[w++] = make_float2(c, __int_as_float(pidx));
                }
            }
    }
    __syncthreads();
    // rank slots by nnz (descending, ties by index); split top NSPLIT across thread pairs
    if (valid) {
        int rank = 0;
        for (int j = 0; j < 99; j++)
            if (scnt[j] > cnt || (scnt[j] == cnt && j < t)) rank++;
        int off = soff[t];
        int dst = zmap(t);
        if (rank < NSPLIT) {
            int p0 = 2 * rank;
            int c1 = (cnt + 1) >> 1;
            g_toff[p0] = off;          g_tcnt[p0] = c1;       g_tdst[p0] = dst;  g_tpair[p0] = 1;
            g_toff[p0 + 1] = off + c1; g_tcnt[p0 + 1] = cnt - c1; g_tdst[p0 + 1] = -1; g_tpair[p0 + 1] = 0;
        } else {
            int p = 2 * NSPLIT + (rank - NSPLIT);   // 58..127
            g_toff[p] = off; g_tcnt[p] = cnt; g_tdst[p] = dst; g_tpair[p] = 0;
        }
    }
}

// ================= main kernel: 256 threads, role-split, edge pairs =================
__device__ __forceinline__ float fsig(float v) { return 1.0f / (1.0f + __expf(-v)); }

__global__ void __launch_bounds__(256, 5)
cg_main_kernel(const float* __restrict__ x, const float* __restrict__ y,
               const float* __restrict__ wcg, const float* __restrict__ bcg,
               const float* __restrict__ wall, const float* __restrict__ ball,
               float* __restrict__ out) {
    __shared__ float2 snz[NZ_MAX];
    __shared__ float sProd[8][256];                    // per-warp product tables
    __shared__ __align__(16) float sZ[2][2][104];      // [pair parity][edge-in-pair]
    __shared__ float sWall[35];
    __shared__ float sBall[4];

    int t = threadIdx.x;
    int w = t >> 5, lane = t & 31;
    int total = g_total;
    for (int i = t; i < total; i += 256) snz[i] = g_nz[i];
    if (t < 35) sWall[t] = wall[t];
    if (t < 4) sBall[t] = ball[t];

    // phase-1 task: table repeats every 128 threads; upper half handles edge+1
    int tt = t & 127;
    int myE = t >> 7;                      // 0 or 1 within pair
    int toff = g_toff[tt], tcnt = g_tcnt[tt], tdst = g_tdst[tt], tpair = g_tpair[tt];

    // role-split weights in a SHARED register array (role is warp-uniform)
    // role A (t<128, channel t):    rw0-3=w0*, rw4=b0, rw5-8=a*, rw9=b1, rw10-15=uw0-5
    // role B (t>=128, chan t-128):  rw0-3=c*,  rw4=b2, rw5-11=vw0-6
    float rw[16];
    int ch;
    if (t < 128) {
        ch = t;
        rw[0] = wcg[ch]; rw[1] = wcg[128 + ch]; rw[2] = wcg[256 + ch]; rw[3] = wcg[384 + ch];
        rw[4] = bcg[ch];
        rw[5] = wcg[512 + ch]; rw[6] = wcg[768 + ch]; rw[7] = wcg[1024 + ch]; rw[8] = wcg[1280 + ch];
        rw[9] = bcg[128 + ch];
        rw[10] = wcg[1536 + ch]; rw[11] = wcg[1664 + ch]; rw[12] = wcg[1792 + ch];
        rw[13] = wcg[1920 + ch]; rw[14] = wcg[2048 + ch]; rw[15] = wcg[2176 + ch];
    } else {
        ch = t - 128;
        rw[0] = wcg[640 + ch]; rw[1] = wcg[896 + ch]; rw[2] = wcg[1152 + ch]; rw[3] = wcg[1408 + ch];
        rw[4] = bcg[256 + ch];
        rw[5] = wcg[2304 + ch]; rw[6] = wcg[2432 + ch]; rw[7] = wcg[2560 + ch];
        rw[8] = wcg[2688 + ch]; rw[9] = wcg[2816 + ch]; rw[10] = wcg[2944 + ch];
        rw[11] = wcg[3072 + ch];
        rw[12] = 0.f; rw[13] = 0.f; rw[14] = 0.f; rw[15] = 0.f;
    }

    int e0 = blockIdx.x * EPB;
    // warp w's edge within the pair: 0 for warps 0-3, 1 for warps 4-7
    int weoff = (w >= 4) ? 1 : 0;
    float pre;
    {
        int e = e0 + weoff;
        pre = (lane < 16) ? x[(size_t)e * 16 + lane] : y[(size_t)e * 16 + (lane - 16)];
    }

    // order cooperative snz/sWall/sBall loads before any phase-1/phase-2 reads
    __syncthreads();

    for (int pi = 0; pi < PAIRS; ++pi) {
        int eb = e0 + 2 * pi;
        // each warp builds the product table for its assigned edge
        float v = pre;
#pragma unroll
        for (int r = 0; r < 8; r++) {
            int p = r * 32 + lane;
            sProd[w][p] = __shfl_sync(0xffffffffu, v, p >> 4) *
                          __shfl_sync(0xffffffffu, v, 16 + (p & 15));
        }
        if (pi + 1 < PAIRS) {
            int en = eb + 2 + weoff;
            pre = (lane < 16) ? x[(size_t)en * 16 + lane] : y[(size_t)en * 16 + (lane - 16)];
        }
        __syncwarp();

        // ---- phase 1: z for both edges of the pair, 256 threads ----
        float* zb = sZ[pi & 1][myE];
        {
            const float* P = sProd[w];
            float acc = 0.0f;
#pragma unroll 4
            for (int n = 0; n < tcnt; n++) {
                float2 ent = snz[toff + n];
                acc = fmaf(ent.x, P[__float_as_int(ent.y)], acc);
            }
            float oth = __shfl_down_sync(0xffffffffu, acc, 1);
            if (tpair) acc += oth;
            if (tdst >= 0) zb[tdst] = acc;
        }
        __syncthreads();   // one barrier per pair

        // ---- phase 2: role-split outputs for both edges ----
        const float S1 = 0.70710678118654752f;   // sqrt(3/6)
        const float S2 = 0.84515425472851657f;   // sqrt(5/7)
        if (t < 128) {
            // role A: rows 0-3 (scv + gated l=1)
#pragma unroll
            for (int el = 0; el < 2; el++) {
                const float* Z = sZ[pi & 1][el];
                float4 z0 = *(const float4*)Z;
                float v0 = fmaf(z0.x, rw[0], fmaf(z0.y, rw[1], fmaf(z0.z, rw[2], z0.w * rw[3])));
                v0 = 0.5f * v0 + rw[4];
                float scv = v0 * fsig(v0);
                float g0 = fmaf(z0.x, rw[5], fmaf(z0.y, rw[6], fmaf(z0.z, rw[7], z0.w * rw[8])));
                g0 = fsig(0.5f * g0 + rw[9]);

                float u0, u1, u2;
                {
                    float4 v4;
                    v4 = *(const float4*)(Z + 4);
                    u0 = v4.x * rw[10]; u1 = v4.y * rw[10]; u2 = v4.z * rw[10]; u0 = fmaf(v4.w, rw[11], u0);
                    v4 = *(const float4*)(Z + 8);
                    u1 = fmaf(v4.x, rw[11], u1); u2 = fmaf(v4.y, rw[11], u2);
                    u0 = fmaf(v4.z, rw[12], u0); u1 = fmaf(v4.w, rw[12], u1);
                    v4 = *(const float4*)(Z + 12);
                    u2 = fmaf(v4.x, rw[12], u2); u0 = fmaf(v4.y, rw[13], u0);
                    u1 = fmaf(v4.z, rw[13], u1); u2 = fmaf(v4.w, rw[13], u2);
                    v4 = *(const float4*)(Z + 16);
                    u0 = fmaf(v4.x, rw[14], u0); u1 = fmaf(v4.y, rw[14], u1);
                    u2 = fmaf(v4.z, rw[14], u2); u0 = fmaf(v4.w, rw[15], u0);
                    float2 v2 = *(const float2*)(Z + 20);
                    u1 = fmaf(v2.x, rw[15], u1); u2 = fmaf(v2.y, rw[15], u2);
                }
                size_t base = ((size_t)(eb + el) * 9) * 128 + ch;
                out[base] = scv;
                float gg = S1 * g0;
                out[base + 128] = u0 * gg;
                out[base + 256] = u1 * gg;
                out[base + 384] = u2 * gg;
            }
            // ---- "all" branch: threads 0-31 cover both edges ----
            if (t < 32) {
                int el = t >> 4;
                int k = t & 15;
                const float* Z = sZ[pi & 1][el];
                float4 z0 = *(const float4*)Z;
                float* oa = out + OUT_ALL_OFF + (size_t)(eb + el) * 16;
                if (k == 0) {
                    float vv = 0.5f * (z0.x * sWall[0] + z0.y * sWall[1] + z0.z * sWall[2] + z0.w * sWall[3]) + sBall[0];
                    oa[0] = vv * fsig(vv);
                } else if (k < 4) {
                    int kk = k - 1;
                    float g = fsig(0.5f * (z0.x * sWall[4] + z0.y * sWall[7] + z0.z * sWall[10] + z0.w * sWall[13]) + sBall[1]);
                    float u = 0.f;
#pragma unroll
                    for (int p = 0; p < 6; p++) u += Z[4 + 3 * p + kk] * sWall[16 + p];
                    oa[k] = 0.70710678118654752f * u * g;
                } else if (k < 9) {
                    int kk = k - 4;
                    float g = fsig(0.5f * (z0.x * sWall[5] + z0.y * sWall[8] + z0.z * sWall[11] + z0.w * sWall[14]) + sBall[2]);
                    float u = 0.f;
#pragma unroll
                    for (int p = 0; p < 7; p++) u += Z[24 + 5 * p + kk] * sWall[22 + p];
                    oa[k] = 0.84515425472851657f * u * g;
                } else {
                    int kk = k - 9;
                    float g = fsig(0.5f * (z0.x * sWall[6] + z0.y * sWall[9] + z0.z * sWall[12] + z0.w * sWall[15]) + sBall[3]);
                    float u = 0.f;
#pragma unroll
                    for (int p = 0; p < 6; p++) u += Z[60 + 7 * p + kk] * sWall[29 + p];
                    oa[k] = 1.08012344973464367f * u * g;   // sqrt(7/6)
                }
            }
        } else {
            // role B: rows 4-8 (gated l=2)
#pragma unroll
            for (int el = 0; el < 2; el++) {
                const float* Z = sZ[pi & 1][el];
                float4 z0 = *(const float4*)Z;
                float g1 = fmaf(z0.x, rw[0], fmaf(z0.y, rw[1], fmaf(z0.z, rw[2], z0.w * rw[3])));
                g1 = fsig(0.5f * g1 + rw[4]);

                float q0, q1, q2, q3, q4;
                {
                    float4 v4;
                    v4 = *(const float4*)(Z + 24);
                    q0 = v4.x * rw[5]; q1 = v4.y * rw[5]; q2 = v4.z * rw[5]; q3 = v4.w * rw[5];
                    v4 = *(const float4*)(Z + 28);
                    q4 = v4.x * rw[5]; q0 = fmaf(v4.y, rw[6], q0); q1 = fmaf(v4.z, rw[6], q1); q2 = fmaf(v4.w, rw[6], q2);
                    v4 = *(const float4*)(Z + 32);
                    q3 = fmaf(v4.x, rw[6], q3); q4 = fmaf(v4.y, rw[6], q4); q0 = fmaf(v4.z, rw[7], q0); q1 = fmaf(v4.w, rw[7], q1);
                    v4 = *(const float4*)(Z + 36);
                    q2 = fmaf(v4.x, rw[7], q2); q3 = fmaf(v4.y, rw[7], q3); q4 = fmaf(v4.z, rw[7], q4); q0 = fmaf(v4.w, rw[8], q0);
                    v4 = *(const float4*)(Z + 40);
                    q1 = fmaf(v4.x, rw[8], q1); q2 = fmaf(v4.y, rw[8], q2); q3 = fmaf(v4.z, rw[8], q3); q4 = fmaf(v4.w, rw[8], q4);
                    v4 = *(const float4*)(Z + 44);
                    q0 = fmaf(v4.x, rw[9], q0); q1 = fmaf(v4.y, rw[9], q1); q2 = fmaf(v4.z, rw[9], q2); q3 = fmaf(v4.w, rw[9], q3);
                    v4 = *(const float4*)(Z + 48);
                    q4 = fmaf(v4.x, rw[9], q4); q0 = fmaf(v4.y, rw[10], q0); q1 = fmaf(v4.z, rw[10], q1); q2 = fmaf(v4.w, rw[10], q2);
                    v4 = *(const float4*)(Z + 52);
                    q3 = fmaf(v4.x, rw[10], q3); q4 = fmaf(v4.y, rw[10], q4); q0 = fmaf(v4.z, rw[11], q0); q1 = fmaf(v4.w, rw[11], q1);
                    v4 = *(const float4*)(Z + 56);   // Z[59] is padding (lane discarded)
                    q2 = fmaf(v4.x, rw[11], q2); q3 = fmaf(v4.y, rw[11], q3); q4 = fmaf(v4.z, rw[11], q4);
                }
                size_t base = ((size_t)(eb + el) * 9) * 128 + ch;
                float hh = S2 * g1;
                out[base + 512] = q0 * hh;
                out[base + 640] = q1 * hh;
                out[base + 768] = q2 * hh;
                out[base + 896] = q3 * hh;
                out[base + 1024] = q4 * hh;
            }
        }
        // no trailing barrier: ping-pong over pair parity + the per-pair barrier
        // give the needed ordering (reaching pair pi+2's phase-1 writes requires
        // passing pair pi+1's barrier, which is after all pair-pi phase-2 reads).
    }
}

extern "C" void kernel_launch(void* const* d_in, const int* in_sizes, int n_in,
                              void* d_out, int out_size) {
    const float* x    = (const float*)d_in[0];
    const float* y    = (const float*)d_in[1];
    const float* wcg  = (const float*)d_in[2];
    const float* bcg  = (const float*)d_in[3];
    const float* wall = (const float*)d_in[4];
    const float* ball = (const float*)d_in[5];
    float* out = (float*)d_out;

    w3j_init_kernel<<<23, 256>>>();
    w3j_compress_kernel<<<1, 128>>>();
    cg_main_kernel<<<GRID, 256>>>(x, y, wcg, bcg, wall, ball, out);
}

// round 14
// speedup vs baseline: 1.3506x; 1.1092x over previous
#include <cuda_runtime.h>
#include <math.h>

#define EDGES 65536
#define GRID  4096
#define EPB   (EDGES / GRID)   // 16 edges per block
#define PAIRS (EPB / 2)        // 8 edge-pairs per block
#define NZ_CAP 1900
#define OUT_ALL_OFF ((size_t)EDGES * 9 * 128)   // 75497472
#define NSPLIT 29

// ===================== compile-time Wigner-3j + task-table generator =====================
namespace gen {

constexpr int KLA[23]  = {0,1,2,3, 0,1,1,2,2,3, 0,1,1,2,2,3,3, 0,1,2,2,3,3};
constexpr int KLB[23]  = {0,1,2,3, 1,0,2,1,3,2, 2,1,3,0,2,1,3, 3,2,1,3,0,2};
constexpr int KLO[23]  = {0,0,0,0, 1,1,1,1,1,1, 2,2,2,2,2,2,2, 3,3,3,3,3,3};
constexpr int KOFF[23] = {0,1,10,35, 84,93,102,147,192,297,
                          402,427,472,577,602,727,832,
                          1077,1126,1231,1336,1581,1630};
constexpr double FACT[11] = {1.,1.,2.,6.,24.,120.,720.,5040.,40320.,362880.,3628800.};

constexpr double csqrt(double x) {
    if (x <= 0.0) return 0.0;
    double g = (x < 1.0) ? 1.0 : x;
    for (int i = 0; i < 200; i++) g = 0.5 * (g + x / g);
    return g;
}
constexpr int imax2(int a, int b) { return a > b ? a : b; }
constexpr int imin2(int a, int b) { return a < b ? a : b; }

constexpr double su2cg(int j1, int m1, int j2, int m2, int j3, int m3) {
    if (m3 != m1 + m2) return 0.0;
    double pref = csqrt((2.0 * j3 + 1.0) * FACT[j3 + j1 - j2] * FACT[j3 - j1 + j2] *
                        FACT[j1 + j2 - j3] / FACT[j1 + j2 + j3 + 1]);
    pref = pref * csqrt(FACT[j3 + m3] * FACT[j3 - m3] * FACT[j1 - m1] * FACT[j1 + m1] *
                        FACT[j2 - m2] * FACT[j2 + m2]);
    int kmin = imax2(0, imax2(j2 - j3 - m1, j1 - j3 + m2));
    int kmax = imin2(j1 + j2 - j3, imin2(j1 - m1, j2 + m2));
    double s = 0.0;
    for (int k = kmin; k <= kmax; k++) {
        double term = 1.0 / (FACT[k] * FACT[j1 + j2 - j3 - k] * FACT[j1 - m1 - k] *
                             FACT[j2 + m2 - k] * FACT[j3 - j2 + m1 + k] * FACT[j3 - j1 - m2 + k]);
        s += (k & 1) ? -term : term;
    }
    return pref * s;
}

struct CD { double re; double im; };
constexpr CD cmulc(CD a, CD b) {
    return CD{a.re * b.re - a.im * b.im, a.re * b.im + a.im * b.re};
}
constexpr CD negip(int l) {
    int m = l & 3;
    return m == 0 ? CD{1, 0} : m == 1 ? CD{0, -1} : m == 2 ? CD{-1, 0} : CD{0, 1};
}
constexpr double RS = 0.70710678118654752440;

struct QE { int n; int idx[2]; CD v[2]; };

constexpr QE qcol(int l, int c) {
    QE q{};
    CD pref = negip(l);
    int mu = c - l;
    if (mu == 0) { q.n = 1; q.idx[0] = l; q.v[0] = pref; return q; }
    if (mu > 0) {
        q.n = 2;
        q.idx[0] = l - mu; q.v[0] = CD{pref.re * RS, pref.im * RS};
        double sg = (mu & 1) ? -1.0 : 1.0;
        q.idx[1] = l + mu; q.v[1] = CD{pref.re * sg * RS, pref.im * sg * RS};
        return q;
    }
    int a = -mu;
    q.n = 2;
    q.idx[0] = l - a; q.v[0] = cmulc(pref, CD{0.0, -RS});
    double sg = (a & 1) ? -1.0 : 1.0;
    q.idx[1] = l + a; q.v[1] = cmulc(pref, CD{0.0, sg * RS});
    return q;
}

constexpr QE qrow(int l, int r) {
    QE q{};
    CD pref = negip(l);
    int mu = r - l;
    if (mu == 0) { q.n = 1; q.idx[0] = l; q.v[0] = pref; return q; }
    if (mu < 0) {
        int a = -mu;
        q.n = 2;
        q.idx[0] = l + a; q.v[0] = CD{pref.re * RS, pref.im * RS};
        q.idx[1] = l - a; q.v[1] = cmulc(pref, CD{0.0, -RS});
        return q;
    }
    double sg = (mu & 1) ? -1.0 : 1.0;
    q.n = 2;
    q.idx[0] = l + mu; q.v[0] = CD{pref.re * sg * RS, pref.im * sg * RS};
    q.idx[1] = l - mu; q.v[1] = cmulc(pref, CD{0.0, sg * RS});
    return q;
}

struct SK { int key; int k; };
constexpr SK sdec(int t) {
    if (t < 4)  return SK{t, 0};
    if (t < 22) { int q = t - 4;  return SK{4 + q / 3, q % 3}; }
    if (t < 57) { int q = t - 22; return SK{10 + q / 5, q % 5}; }
    { int q = t - 57; return SK{17 + q / 7, q % 7}; }
}
constexpr int zmapc(int s) { return s + (s >= 22 ? 2 : 0) + (s >= 57 ? 1 : 0); }

struct Tables {
    int total;
    float nzc[NZ_CAP];
    int   nzi[NZ_CAP];
    int toff[128];
    int tcnt[128];
    int tdst[128];
    int tprs[128];
};

constexpr Tables make_tables() {
    Tables T{};
    double w3j[1875] = {};
    for (int key = 0; key < 23; key++) {
        int la = KLA[key], lb = KLB[key], lo = KLO[key];
        int na = 2 * la + 1, nb = 2 * lb + 1, no = 2 * lo + 1;
        double C[343] = {};
        double Cr[245] = {};
        for (int i = 0; i < na; i++)
            for (int k = 0; k < nb; k++)
                for (int m = 0; m < no; m++) {
                    int m1 = i - la, m2 = k - lb, m3 = m - lo;
                    C[(i * nb + k) * no + m] =
                        (m3 == m1 + m2) ? su2cg(la, m1, lb, m2, lo, m3) : 0.0;
                }
        double norm2 = 0.0;
        for (int ja = 0; ja < na; ja++)
            for (int jb = 0; jb < nb; jb++)
                for (int jn = 0; jn < no; jn++) {
                    QE q1 = qcol(la, ja), q2 = qcol(lb, jb), q3 = qrow(lo, jn);
                    double accre = 0.0;
                    for (int a = 0; a < q1.n; a++)
                        for (int b = 0; b < q2.n; b++)
                            for (int c = 0; c < q3.n; c++) {
                                CD qq = cmulc(cmulc(q1.v[a], q2.v[b]),
                                              CD{q3.v[c].re, -q3.v[c].im});
                                double cv = C[(q1.idx[a] * nb + q2.idx[b]) * no + q3.idx[c]];
                                accre += qq.re * cv;
                            }
                    Cr[(ja * nb + jb) * no + jn] = accre;
                    norm2 += accre * accre;
                }
        double inv = 1.0 / csqrt(norm2);
        int n = na * nb * no;
        for (int idx = 0; idx < n; idx++) w3j[KOFF[key] + idx] = Cr[idx] * inv;
    }

    // per-slot nonzero counts + offsets
    int scnt[99] = {};
    int soff[99] = {};
    for (int s = 0; s < 99; s++) {
        SK sk = sdec(s);
        int la = KLA[sk.key], lb = KLB[sk.key];
        int na = 2 * la + 1, nb = 2 * lb + 1, no = 2 * KLO[sk.key] + 1;
        int cnt = 0;
        for (int i = 0; i < na; i++)
            for (int j = 0; j < nb; j++) {
                double c = w3j[KOFF[sk.key] + (i * nb + j) * no + sk.k];
                if (c > 1e-10 || c < -1e-10) cnt++;
            }
        scnt[s] = cnt;
    }
    int acc = 0;
    for (int s = 0; s < 99; s++) { soff[s] = acc; acc += scnt[s]; }
    T.total = acc;

    // nz entries in slot order
    for (int s = 0; s < 99; s++) {
        SK sk = sdec(s);
        int la = KLA[sk.key], lb = KLB[sk.key];
        int na = 2 * la + 1, nb = 2 * lb + 1, no = 2 * KLO[sk.key] + 1;
        int wpos = soff[s];
        for (int i = 0; i < na; i++)
            for (int j = 0; j < nb; j++) {
                double c = w3j[KOFF[sk.key] + (i * nb + j) * no + sk.k];
                if (c > 1e-10 || c < -1e-10) {
                    T.nzc[wpos] = (float)c;
                    T.nzi[wpos] = (la * la + i) * 16 + (lb * lb + j);
                    wpos++;
                }
            }
    }

    // rank slots by nnz desc (stable); split top NSPLIT across even/odd thread pairs
    for (int s = 0; s < 99; s++) {
        int rank = 0;
        for (int j = 0; j < 99; j++)
            if (scnt[j] > scnt[s] || (scnt[j] == scnt[s] && j < s)) rank++;
        int off = soff[s], cnt = scnt[s], dst = zmapc(s);
        if (rank < NSPLIT) {
            int p0 = 2 * rank;
            int c1 = (cnt + 1) >> 1;
            T.toff[p0] = off;           T.tcnt[p0] = c1;        T.tdst[p0] = dst;  T.tprs[p0] = 1;
            T.toff[p0 + 1] = off + c1;  T.tcnt[p0 + 1] = cnt - c1; T.tdst[p0 + 1] = -1; T.tprs[p0 + 1] = 0;
        } else {
            int p = 2 * NSPLIT + (rank - NSPLIT);   // 58..127
            T.toff[p] = off; T.tcnt[p] = cnt; T.tdst[p] = dst; T.tprs[p] = 0;
        }
    }
    return T;
}

} // namespace gen

__device__ constexpr gen::Tables g_tab = gen::make_tables();

// ================= main kernel: 256 threads, role-split, edge pairs =================
__device__ __forceinline__ float fsig(float v) { return 1.0f / (1.0f + __expf(-v)); }

__global__ void __launch_bounds__(256, 5)
cg_main_kernel(const float* __restrict__ x, const float* __restrict__ y,
               const float* __restrict__ wcg, const float* __restrict__ bcg,
               const float* __restrict__ wall, const float* __restrict__ ball,
               float* __restrict__ out) {
    __shared__ float2 snz[NZ_CAP];
    __shared__ float sProd[8][256];                    // per-warp product tables
    __shared__ __align__(16) float sZ[2][2][104];      // [pair parity][edge-in-pair]
    __shared__ float sWall[35];
    __shared__ float sBall[4];

    int t = threadIdx.x;
    int w = t >> 5, lane = t & 31;
    int total = g_tab.total;
    for (int i = t; i < total; i += 256)
        snz[i] = make_float2(g_tab.nzc[i], __int_as_float(g_tab.nzi[i]));
    if (t < 35) sWall[t] = wall[t];
    if (t < 4) sBall[t] = ball[t];

    // phase-1 task: table repeats every 128 threads; upper half handles edge+1
    int tt = t & 127;
    int myE = t >> 7;                      // 0 or 1 within pair
    int toff = g_tab.toff[tt], tcnt = g_tab.tcnt[tt];
    int tdst = g_tab.tdst[tt], tpair = g_tab.tprs[tt];

    // role-split weights in one register array (role is warp-uniform)
    float rw[16];
    int ch;
    if (t < 128) {
        ch = t;
        rw[0] = wcg[ch]; rw[1] = wcg[128 + ch]; rw[2] = wcg[256 + ch]; rw[3] = wcg[384 + ch];
        rw[4] = bcg[ch];
        rw[5] = wcg[512 + ch]; rw[6] = wcg[768 + ch]; rw[7] = wcg[1024 + ch]; rw[8] = wcg[1280 + ch];
        rw[9] = bcg[128 + ch];
        rw[10] = wcg[1536 + ch]; rw[11] = wcg[1664 + ch]; rw[12] = wcg[1792 + ch];
        rw[13] = wcg[1920 + ch]; rw[14] = wcg[2048 + ch]; rw[15] = wcg[2176 + ch];
    } else {
        ch = t - 128;
        rw[0] = wcg[640 + ch]; rw[1] = wcg[896 + ch]; rw[2] = wcg[1152 + ch]; rw[3] = wcg[1408 + ch];
        rw[4] = bcg[256 + ch];
        rw[5] = wcg[2304 + ch]; rw[6] = wcg[2432 + ch]; rw[7] = wcg[2560 + ch];
        rw[8] = wcg[2688 + ch]; rw[9] = wcg[2816 + ch]; rw[10] = wcg[2944 + ch];
        rw[11] = wcg[3072 + ch];
        rw[12] = 0.f; rw[13] = 0.f; rw[14] = 0.f; rw[15] = 0.f;
    }

    int e0 = blockIdx.x * EPB;
    // warp w's edge within the pair: 0 for warps 0-3, 1 for warps 4-7
    int weoff = (w >= 4) ? 1 : 0;
    float pre;
    {
        int e = e0 + weoff;
        pre = (lane < 16) ? x[(size_t)e * 16 + lane] : y[(size_t)e * 16 + (lane - 16)];
    }

    // order cooperative snz/sWall/sBall loads before any phase-1/phase-2 reads
    __syncthreads();

    for (int pi = 0; pi < PAIRS; ++pi) {
        int eb = e0 + 2 * pi;
        // each warp builds the product table for its assigned edge
        float v = pre;
#pragma unroll
        for (int r = 0; r < 8; r++) {
            int p = r * 32 + lane;
            sProd[w][p] = __shfl_sync(0xffffffffu, v, p >> 4) *
                          __shfl_sync(0xffffffffu, v, 16 + (p & 15));
        }
        if (pi + 1 < PAIRS) {
            int en = eb + 2 + weoff;
            pre = (lane < 16) ? x[(size_t)en * 16 + lane] : y[(size_t)en * 16 + (lane - 16)];
        }
        __syncwarp();

        // ---- phase 1: z for both edges of the pair, 256 threads ----
        float* zb = sZ[pi & 1][myE];
        {
            const float* P = sProd[w];
            float acc = 0.0f;
#pragma unroll 4
            for (int n = 0; n < tcnt; n++) {
                float2 ent = snz[toff + n];
                acc = fmaf(ent.x, P[__float_as_int(ent.y)], acc);
            }
            float oth = __shfl_down_sync(0xffffffffu, acc, 1);
            if (tpair) acc += oth;
            if (tdst >= 0) zb[tdst] = acc;
        }
        __syncthreads();   // one barrier per pair

        // ---- phase 2: role-split outputs for both edges ----
        const float S1 = 0.70710678118654752f;   // sqrt(3/6)
        const float S2 = 0.84515425472851657f;   // sqrt(5/7)
        if (t < 128) {
            // role A: rows 0-3 (scv + gated l=1)
#pragma unroll
            for (int el = 0; el < 2; el++) {
                const float* Z = sZ[pi & 1][el];
                float4 z0 = *(const float4*)Z;
                float v0 = fmaf(z0.x, rw[0], fmaf(z0.y, rw[1], fmaf(z0.z, rw[2], z0.w * rw[3])));
                v0 = 0.5f * v0 + rw[4];
                float scv = v0 * fsig(v0);
                float g0 = fmaf(z0.x, rw[5], fmaf(z0.y, rw[6], fmaf(z0.z, rw[7], z0.w * rw[8])));
                g0 = fsig(0.5f * g0 + rw[9]);

                float u0, u1, u2;
                {
                    float4 v4;
                    v4 = *(const float4*)(Z + 4);
                    u0 = v4.x * rw[10]; u1 = v4.y * rw[10]; u2 = v4.z * rw[10]; u0 = fmaf(v4.w, rw[11], u0);
                    v4 = *(const float4*)(Z + 8);
                    u1 = fmaf(v4.x, rw[11], u1); u2 = fmaf(v4.y, rw[11], u2);
                    u0 = fmaf(v4.z, rw[12], u0); u1 = fmaf(v4.w, rw[12], u1);
                    v4 = *(const float4*)(Z + 12);
                    u2 = fmaf(v4.x, rw[12], u2); u0 = fmaf(v4.y, rw[13], u0);
                    u1 = fmaf(v4.z, rw[13], u1); u2 = fmaf(v4.w, rw[13], u2);
                    v4 = *(const float4*)(Z + 16);
                    u0 = fmaf(v4.x, rw[14], u0); u1 = fmaf(v4.y, rw[14], u1);
                    u2 = fmaf(v4.z, rw[14], u2); u0 = fmaf(v4.w, rw[15], u0);
                    float2 v2 = *(const float2*)(Z + 20);
                    u1 = fmaf(v2.x, rw[15], u1); u2 = fmaf(v2.y, rw[15], u2);
                }
                size_t base = ((size_t)(eb + el) * 9) * 128 + ch;
                out[base] = scv;
                float gg = S1 * g0;
                out[base + 128] = u0 * gg;
                out[base + 256] = u1 * gg;
                out[base + 384] = u2 * gg;
            }
            // ---- "all" branch: threads 0-31 cover both edges ----
            if (t < 32) {
                int el = t >> 4;
                int k = t & 15;
                const float* Z = sZ[pi & 1][el];
                float4 z0 = *(const float4*)Z;
                float* oa = out + OUT_ALL_OFF + (size_t)(eb + el) * 16;
                if (k == 0) {
                    float vv = 0.5f * (z0.x * sWall[0] + z0.y * sWall[1] + z0.z * sWall[2] + z0.w * sWall[3]) + sBall[0];
                    oa[0] = vv * fsig(vv);
                } else if (k < 4) {
                    int kk = k - 1;
                    float g = fsig(0.5f * (z0.x * sWall[4] + z0.y * sWall[7] + z0.z * sWall[10] + z0.w * sWall[13]) + sBall[1]);
                    float u = 0.f;
#pragma unroll
                    for (int p = 0; p < 6; p++) u += Z[4 + 3 * p + kk] * sWall[16 + p];
                    oa[k] = 0.70710678118654752f * u * g;
                } else if (k < 9) {
                    int kk = k - 4;
                    float g = fsig(0.5f * (z0.x * sWall[5] + z0.y * sWall[8] + z0.z * sWall[11] + z0.w * sWall[14]) + sBall[2]);
                    float u = 0.f;
#pragma unroll
                    for (int p = 0; p < 7; p++) u += Z[24 + 5 * p + kk] * sWall[22 + p];
                    oa[k] = 0.84515425472851657f * u * g;
                } else {
                    int kk = k - 9;
                    float g = fsig(0.5f * (z0.x * sWall[6] + z0.y * sWall[9] + z0.z * sWall[12] + z0.w * sWall[15]) + sBall[3]);
                    float u = 0.f;
#pragma unroll
                    for (int p = 0; p < 6; p++) u += Z[60 + 7 * p + kk] * sWall[29 + p];
                    oa[k] = 1.08012344973464367f * u * g;   // sqrt(7/6)
                }
            }
        } else {
            // role B: rows 4-8 (gated l=2)
#pragma unroll
            for (int el = 0; el < 2; el++) {
                const float* Z = sZ[pi & 1][el];
                float4 z0 = *(const float4*)Z;
                float g1 = fmaf(z0.x, rw[0], fmaf(z0.y, rw[1], fmaf(z0.z, rw[2], z0.w * rw[3])));
                g1 = fsig(0.5f * g1 + rw[4]);

                float q0, q1, q2, q3, q4;
                {
                    float4 v4;
                    v4 = *(const float4*)(Z + 24);
                    q0 = v4.x * rw[5]; q1 = v4.y * rw[5]; q2 = v4.z * rw[5]; q3 = v4.w * rw[5];
                    v4 = *(const float4*)(Z + 28);
                    q4 = v4.x * rw[5]; q0 = fmaf(v4.y, rw[6], q0); q1 = fmaf(v4.z, rw[6], q1); q2 = fmaf(v4.w, rw[6], q2);
                    v4 = *(const float4*)(Z + 32);
                    q3 = fmaf(v4.x, rw[6], q3); q4 = fmaf(v4.y, rw[6], q4); q0 = fmaf(v4.z, rw[7], q0); q1 = fmaf(v4.w, rw[7], q1);
                    v4 = *(const float4*)(Z + 36);
                    q2 = fmaf(v4.x, rw[7], q2); q3 = fmaf(v4.y, rw[7], q3); q4 = fmaf(v4.z, rw[7], q4); q0 = fmaf(v4.w, rw[8], q0);
                    v4 = *(const float4*)(Z + 40);
                    q1 = fmaf(v4.x, rw[8], q1); q2 = fmaf(v4.y, rw[8], q2); q3 = fmaf(v4.z, rw[8], q3); q4 = fmaf(v4.w, rw[8], q4);
                    v4 = *(const float4*)(Z + 44);
                    q0 = fmaf(v4.x, rw[9], q0); q1 = fmaf(v4.y, rw[9], q1); q2 = fmaf(v4.z, rw[9], q2); q3 = fmaf(v4.w, rw[9], q3);
                    v4 = *(const float4*)(Z + 48);
                    q4 = fmaf(v4.x, rw[9], q4); q0 = fmaf(v4.y, rw[10], q0); q1 = fmaf(v4.z, rw[10], q1); q2 = fmaf(v4.w, rw[10], q2);
                    v4 = *(const float4*)(Z + 52);
                    q3 = fmaf(v4.x, rw[10], q3); q4 = fmaf(v4.y, rw[10], q4); q0 = fmaf(v4.z, rw[11], q0); q1 = fmaf(v4.w, rw[11], q1);
                    v4 = *(const float4*)(Z + 56);   // Z[59] is padding (lane discarded)
                    q2 = fmaf(v4.x, rw[11], q2); q3 = fmaf(v4.y, rw[11], q3); q4 = fmaf(v4.z, rw[11], q4);
                }
                size_t base = ((size_t)(eb + el) * 9) * 128 + ch;
                float hh = S2 * g1;
                out[base + 512] = q0 * hh;
                out[base + 640] = q1 * hh;
                out[base + 768] = q2 * hh;
                out[base + 896] = q3 * hh;
                out[base + 1024] = q4 * hh;
            }
        }
        // no trailing barrier: ping-pong over pair parity + the per-pair barrier
        // give the needed ordering (reaching pair pi+2's phase-1 writes requires
        // passing pair pi+1's barrier, which is after all pair-pi phase-2 reads).
    }
}

extern "C" void kernel_launch(void* const* d_in, const int* in_sizes, int n_in,
                              void* d_out, int out_size) {
    const float* x    = (const float*)d_in[0];
    const float* y    = (const float*)d_in[1];
    const float* wcg  = (const float*)d_in[2];
    const float* bcg  = (const float*)d_in[3];
    const float* wall = (const float*)d_in[4];
    const float* ball = (const float*)d_in[5];
    float* out = (float*)d_out;

    cg_main_kernel<<<GRID, 256>>>(x, y, wcg, bcg, wall, ball, out);
}

// round 15
// speedup vs baseline: 1.4219x; 1.0528x over previous
#include <cuda_runtime.h>
#include <math.h>

#define EDGES 65536
#define GRID  4096
#define EPB   (EDGES / GRID)   // 16 edges per block
#define PAIRS (EPB / 2)        // 8 edge-pairs per block
#define OUT_ALL_OFF ((size_t)EDGES * 9 * 128)   // 75497472
#define NSPLIT 29
#define MAXC 24                // padded max entries per task (constexpr-checked)

// ===================== compile-time Wigner-3j + task-table generator =====================
namespace gen {

constexpr int KLA[23]  = {0,1,2,3, 0,1,1,2,2,3, 0,1,1,2,2,3,3, 0,1,2,2,3,3};
constexpr int KLB[23]  = {0,1,2,3, 1,0,2,1,3,2, 2,1,3,0,2,1,3, 3,2,1,3,0,2};
constexpr int KLO[23]  = {0,0,0,0, 1,1,1,1,1,1, 2,2,2,2,2,2,2, 3,3,3,3,3,3};
constexpr int KOFF[23] = {0,1,10,35, 84,93,102,147,192,297,
                          402,427,472,577,602,727,832,
                          1077,1126,1231,1336,1581,1630};
constexpr double FACT[11] = {1.,1.,2.,6.,24.,120.,720.,5040.,40320.,362880.,3628800.};

constexpr double csqrt(double x) {
    if (x <= 0.0) return 0.0;
    double g = (x < 1.0) ? 1.0 : x;
    for (int i = 0; i < 200; i++) g = 0.5 * (g + x / g);
    return g;
}
constexpr int imax2(int a, int b) { return a > b ? a : b; }
constexpr int imin2(int a, int b) { return a < b ? a : b; }

constexpr double su2cg(int j1, int m1, int j2, int m2, int j3, int m3) {
    if (m3 != m1 + m2) return 0.0;
    double pref = csqrt((2.0 * j3 + 1.0) * FACT[j3 + j1 - j2] * FACT[j3 - j1 + j2] *
                        FACT[j1 + j2 - j3] / FACT[j1 + j2 + j3 + 1]);
    pref = pref * csqrt(FACT[j3 + m3] * FACT[j3 - m3] * FACT[j1 - m1] * FACT[j1 + m1] *
                        FACT[j2 - m2] * FACT[j2 + m2]);
    int kmin = imax2(0, imax2(j2 - j3 - m1, j1 - j3 + m2));
    int kmax = imin2(j1 + j2 - j3, imin2(j1 - m1, j2 + m2));
    double s = 0.0;
    for (int k = kmin; k <= kmax; k++) {
        double term = 1.0 / (FACT[k] * FACT[j1 + j2 - j3 - k] * FACT[j1 - m1 - k] *
                             FACT[j2 + m2 - k] * FACT[j3 - j2 + m1 + k] * FACT[j3 - j1 - m2 + k]);
        s += (k & 1) ? -term : term;
    }
    return pref * s;
}

struct CD { double re; double im; };
constexpr CD cmulc(CD a, CD b) {
    return CD{a.re * b.re - a.im * b.im, a.re * b.im + a.im * b.re};
}
constexpr CD negip(int l) {
    int m = l & 3;
    return m == 0 ? CD{1, 0} : m == 1 ? CD{0, -1} : m == 2 ? CD{-1, 0} : CD{0, 1};
}
constexpr double RS = 0.70710678118654752440;

struct QE { int n; int idx[2]; CD v[2]; };

constexpr QE qcol(int l, int c) {
    QE q{};
    CD pref = negip(l);
    int mu = c - l;
    if (mu == 0) { q.n = 1; q.idx[0] = l; q.v[0] = pref; return q; }
    if (mu > 0) {
        q.n = 2;
        q.idx[0] = l - mu; q.v[0] = CD{pref.re * RS, pref.im * RS};
        double sg = (mu & 1) ? -1.0 : 1.0;
        q.idx[1] = l + mu; q.v[1] = CD{pref.re * sg * RS, pref.im * sg * RS};
        return q;
    }
    int a = -mu;
    q.n = 2;
    q.idx[0] = l - a; q.v[0] = cmulc(pref, CD{0.0, -RS});
    double sg = (a & 1) ? -1.0 : 1.0;
    q.idx[1] = l + a; q.v[1] = cmulc(pref, CD{0.0, sg * RS});
    return q;
}

constexpr QE qrow(int l, int r) {
    QE q{};
    CD pref = negip(l);
    int mu = r - l;
    if (mu == 0) { q.n = 1; q.idx[0] = l; q.v[0] = pref; return q; }
    if (mu < 0) {
        int a = -mu;
        q.n = 2;
        q.idx[0] = l + a; q.v[0] = CD{pref.re * RS, pref.im * RS};
        q.idx[1] = l - a; q.v[1] = cmulc(pref, CD{0.0, -RS});
        return q;
    }
    double sg = (mu & 1) ? -1.0 : 1.0;
    q.n = 2;
    q.idx[0] = l + mu; q.v[0] = CD{pref.re * sg * RS, pref.im * sg * RS};
    q.idx[1] = l - mu; q.v[1] = cmulc(pref, CD{0.0, sg * RS});
    return q;
}

struct SK { int key; int k; };
constexpr SK sdec(int t) {
    if (t < 4)  return SK{t, 0};
    if (t < 22) { int q = t - 4;  return SK{4 + q / 3, q % 3}; }
    if (t < 57) { int q = t - 22; return SK{10 + q / 5, q % 5}; }
    { int q = t - 57; return SK{17 + q / 7, q % 7}; }
}
constexpr int zmapc(int s) { return s + (s >= 22 ? 2 : 0) + (s >= 57 ? 1 : 0); }

struct Tables {
    int wmax[4];             // per warp-group (tasks 32g..32g+31) uniform loop bound
    float cT[MAXC][128];     // transposed coeff streams (zero padded)
    int   sT[MAXC][128];     // packed shuffle sources: srcA | (srcB<<8)
    int tdst[128];
    int tprs[128];
};

constexpr Tables make_tables() {
    Tables T{};
    double w3j[1875] = {};
    for (int key = 0; key < 23; key++) {
        int la = KLA[key], lb = KLB[key], lo = KLO[key];
        int na = 2 * la + 1, nb = 2 * lb + 1, no = 2 * lo + 1;
        double C[343] = {};
        double Cr[245] = {};
        for (int i = 0; i < na; i++)
            for (int k = 0; k < nb; k++)
                for (int m = 0; m < no; m++) {
                    int m1 = i - la, m2 = k - lb, m3 = m - lo;
                    C[(i * nb + k) * no + m] =
                        (m3 == m1 + m2) ? su2cg(la, m1, lb, m2, lo, m3) : 0.0;
                }
        double norm2 = 0.0;
        for (int ja = 0; ja < na; ja++)
            for (int jb = 0; jb < nb; jb++)
                for (int jn = 0; jn < no; jn++) {
                    QE q1 = qcol(la, ja), q2 = qcol(lb, jb), q3 = qrow(lo, jn);
                    double accre = 0.0;
                    for (int a = 0; a < q1.n; a++)
                        for (int b = 0; b < q2.n; b++)
                            for (int c = 0; c < q3.n; c++) {
                                CD qq = cmulc(cmulc(q1.v[a], q2.v[b]),
                                              CD{q3.v[c].re, -q3.v[c].im});
                                double cv = C[(q1.idx[a] * nb + q2.idx[b]) * no + q3.idx[c]];
                                accre += qq.re * cv;
                            }
                    Cr[(ja * nb + jb) * no + jn] = accre;
                    norm2 += accre * accre;
                }
        double inv = 1.0 / csqrt(norm2);
        int n = na * nb * no;
        for (int idx = 0; idx < n; idx++) w3j[KOFF[key] + idx] = Cr[idx] * inv;
    }

    // per-slot nonzero lists
    int scnt[99] = {};
    int soff[99] = {};
    double nzc[1900] = {};
    int    nzs[1900] = {};
    {
        int acc = 0;
        for (int s = 0; s < 99; s++) {
            SK sk = sdec(s);
            int la = KLA[sk.key], lb = KLB[sk.key];
            int na = 2 * la + 1, nb = 2 * lb + 1, no = 2 * KLO[sk.key] + 1;
            soff[s] = acc;
            int cnt = 0;
            for (int i = 0; i < na; i++)
                for (int j = 0; j < nb; j++) {
                    double c = w3j[KOFF[sk.key] + (i * nb + j) * no + sk.k];
                    if (c > 1e-10 || c < -1e-10) {
                        int xi = la * la + i;        // x source lane (0-15)
                        int yj = 16 + lb * lb + j;   // y source lane (16-31)
                        nzc[acc + cnt] = c;
                        nzs[acc + cnt] = xi | (yj << 8);
                        cnt++;
                    }
                }
            scnt[s] = cnt;
            acc += cnt;
        }
    }

    // rank slots by nnz desc (stable); split top NSPLIT across even/odd thread pairs
    int toff[128] = {};
    int tcnt[128] = {};
    for (int s = 0; s < 99; s++) {
        int rank = 0;
        for (int j = 0; j < 99; j++)
            if (scnt[j] > scnt[s] || (scnt[j] == scnt[s] && j < s)) rank++;
        int off = soff[s], cnt = scnt[s], dst = zmapc(s);
        if (rank < NSPLIT) {
            int p0 = 2 * rank;
            int c1 = (cnt + 1) >> 1;
            toff[p0] = off;          tcnt[p0] = c1;       T.tdst[p0] = dst;  T.tprs[p0] = 1;
            toff[p0 + 1] = off + c1; tcnt[p0 + 1] = cnt - c1; T.tdst[p0 + 1] = -1; T.tprs[p0 + 1] = 0;
        } else {
            int p = 2 * NSPLIT + (rank - NSPLIT);   // 58..127
            toff[p] = off; tcnt[p] = cnt; T.tdst[p] = dst; T.tprs[p] = 0;
        }
    }

    // transposed, padded streams + per-warp-group uniform bounds
    for (int g = 0; g < 4; g++) {
        int m = 0;
        for (int p = 32 * g; p < 32 * g + 32; p++) m = imax2(m, tcnt[p]);
        T.wmax[g] = m;
    }
    for (int p = 0; p < 128; p++)
        for (int n = 0; n < MAXC; n++) {
            if (n < tcnt[p]) {
                T.cT[n][p] = (float)nzc[toff[p] + n];   // OOB here = compile error (fail-closed)
                T.sT[n][p] = nzs[toff[p] + n];
            } else {
                T.cT[n][p] = 0.0f;
                T.sT[n][p] = 0;                          // shfl lane 0, coeff 0 -> no-op
            }
        }
    return T;
}

} // namespace gen

__device__ constexpr gen::Tables g_tab = gen::make_tables();

// ================= main kernel: 256 threads, role-split, edge pairs =================
__device__ __forceinline__ float fsig(float v) { return 1.0f / (1.0f + __expf(-v)); }

__global__ void __launch_bounds__(256, 5)
cg_main_kernel(const float* __restrict__ x, const float* __restrict__ y,
               const float* __restrict__ wcg, const float* __restrict__ bcg,
               const float* __restrict__ wall, const float* __restrict__ ball,
               float* __restrict__ out) {
    __shared__ float sCoef[MAXC][128];                 // conflict-free transposed streams
    __shared__ int   sSrc[MAXC][128];
    __shared__ __align__(16) float sZ[2][2][104];      // [pair parity][edge-in-pair]
    __shared__ float sWall[35];
    __shared__ float sBall[4];

    int t = threadIdx.x;
    int w = t >> 5, lane = t & 31;
    for (int i = t; i < MAXC * 128; i += 256) {
        ((float*)sCoef)[i] = ((const float*)g_tab.cT)[i];
        ((int*)sSrc)[i] = ((const int*)g_tab.sT)[i];
    }
    if (t < 35) sWall[t] = wall[t];
    if (t < 4) sBall[t] = ball[t];

    // phase-1 task: table repeats every 128 threads; upper half handles edge+1
    int tt = t & 127;
    int myE = t >> 7;                      // 0 or 1 within pair
    int wm = g_tab.wmax[(t >> 5) & 3];     // warp-uniform loop bound
    int tdst = g_tab.tdst[tt], tpair = g_tab.tprs[tt];

    // role-split weights in one register array (role is warp-uniform)
    float rw[16];
    int ch;
    if (t < 128) {
        ch = t;
        rw[0] = wcg[ch]; rw[1] = wcg[128 + ch]; rw[2] = wcg[256 + ch]; rw[3] = wcg[384 + ch];
        rw[4] = bcg[ch];
        rw[5] = wcg[512 + ch]; rw[6] = wcg[768 + ch]; rw[7] = wcg[1024 + ch]; rw[8] = wcg[1280 + ch];
        rw[9] = bcg[128 + ch];
        rw[10] = wcg[1536 + ch]; rw[11] = wcg[1664 + ch]; rw[12] = wcg[1792 + ch];
        rw[13] = wcg[1920 + ch]; rw[14] = wcg[2048 + ch]; rw[15] = wcg[2176 + ch];
    } else {
        ch = t - 128;
        rw[0] = wcg[640 + ch]; rw[1] = wcg[896 + ch]; rw[2] = wcg[1152 + ch]; rw[3] = wcg[1408 + ch];
        rw[4] = bcg[256 + ch];
        rw[5] = wcg[2304 + ch]; rw[6] = wcg[2432 + ch]; rw[7] = wcg[2560 + ch];
        rw[8] = wcg[2688 + ch]; rw[9] = wcg[2816 + ch]; rw[10] = wcg[2944 + ch];
        rw[11] = wcg[3072 + ch];
        rw[12] = 0.f; rw[13] = 0.f; rw[14] = 0.f; rw[15] = 0.f;
    }

    int e0 = blockIdx.x * EPB;
    // warp w's edge within the pair: 0 for warps 0-3, 1 for warps 4-7
    int weoff = (w >= 4) ? 1 : 0;
    float pre;
    {
        int e = e0 + weoff;
        pre = (lane < 16) ? x[(size_t)e * 16 + lane] : y[(size_t)e * 16 + (lane - 16)];
    }

    // order cooperative stream/sWall/sBall loads before any phase-1/phase-2 reads
    __syncthreads();

    for (int pi = 0; pi < PAIRS; ++pi) {
        int eb = e0 + 2 * pi;
        float v = pre;                                  // this warp's edge x/y
        if (pi + 1 < PAIRS) {
            int en = eb + 2 + weoff;
            pre = (lane < 16) ? x[(size_t)en * 16 + lane] : y[(size_t)en * 16 + (lane - 16)];
        }

        // ---- phase 1: shuffle-gather sparse z (conflict-free LDS, uniform loop) ----
        float* zb = sZ[pi & 1][myE];
        {
            float acc = 0.0f;
            for (int n = 0; n < wm; n++) {
                float c = sCoef[n][tt];
                int s = sSrc[n][tt];
                float xa = __shfl_sync(0xffffffffu, v, s & 31);
                float yb = __shfl_sync(0xffffffffu, v, (s >> 8) & 31);
                acc = fmaf(c, xa * yb, acc);
            }
            float oth = __shfl_down_sync(0xffffffffu, acc, 1);
            if (tpair) acc += oth;
            if (tdst >= 0) zb[tdst] = acc;
        }
        __syncthreads();   // one barrier per pair

        // ---- phase 2: role-split outputs for both edges ----
        const float S1 = 0.70710678118654752f;   // sqrt(3/6)
        const float S2 = 0.84515425472851657f;   // sqrt(5/7)
        if (t < 128) {
            // role A: rows 0-3 (scv + gated l=1)
#pragma unroll
            for (int el = 0; el < 2; el++) {
                const float* Z = sZ[pi & 1][el];
                float4 z0 = *(const float4*)Z;
                float v0 = fmaf(z0.x, rw[0], fmaf(z0.y, rw[1], fmaf(z0.z, rw[2], z0.w * rw[3])));
                v0 = 0.5f * v0 + rw[4];
                float scv = v0 * fsig(v0);
                float g0 = fmaf(z0.x, rw[5], fmaf(z0.y, rw[6], fmaf(z0.z, rw[7], z0.w * rw[8])));
                g0 = fsig(0.5f * g0 + rw[9]);

                float u0, u1, u2;
                {
                    float4 v4;
                    v4 = *(const float4*)(Z + 4);
                    u0 = v4.x * rw[10]; u1 = v4.y * rw[10]; u2 = v4.z * rw[10]; u0 = fmaf(v4.w, rw[11], u0);
                    v4 = *(const float4*)(Z + 8);
                    u1 = fmaf(v4.x, rw[11], u1); u2 = fmaf(v4.y, rw[11], u2);
                    u0 = fmaf(v4.z, rw[12], u0); u1 = fmaf(v4.w, rw[12], u1);
                    v4 = *(const float4*)(Z + 12);
                    u2 = fmaf(v4.x, rw[12], u2); u0 = fmaf(v4.y, rw[13], u0);
                    u1 = fmaf(v4.z, rw[13], u1); u2 = fmaf(v4.w, rw[13], u2);
                    v4 = *(const float4*)(Z + 16);
                    u0 = fmaf(v4.x, rw[14], u0); u1 = fmaf(v4.y, rw[14], u1);
                    u2 = fmaf(v4.z, rw[14], u2); u0 = fmaf(v4.w, rw[15], u0);
                    float2 v2 = *(const float2*)(Z + 20);
                    u1 = fmaf(v2.x, rw[15], u1); u2 = fmaf(v2.y, rw[15], u2);
                }
                size_t base = ((size_t)(eb + el) * 9) * 128 + ch;
                out[base] = scv;
                float gg = S1 * g0;
                out[base + 128] = u0 * gg;
                out[base + 256] = u1 * gg;
                out[base + 384] = u2 * gg;
            }
            // ---- "all" branch: threads 0-31 cover both edges ----
            if (t < 32) {
                int el = t >> 4;
                int k = t & 15;
                const float* Z = sZ[pi & 1][el];
                float4 z0 = *(const float4*)Z;
                float* oa = out + OUT_ALL_OFF + (size_t)(eb + el) * 16;
                if (k == 0) {
                    float vv = 0.5f * (z0.x * sWall[0] + z0.y * sWall[1] + z0.z * sWall[2] + z0.w * sWall[3]) + sBall[0];
                    oa[0] = vv * fsig(vv);
                } else if (k < 4) {
                    int kk = k - 1;
                    float g = fsig(0.5f * (z0.x * sWall[4] + z0.y * sWall[7] + z0.z * sWall[10] + z0.w * sWall[13]) + sBall[1]);
                    float u = 0.f;
#pragma unroll
                    for (int p = 0; p < 6; p++) u += Z[4 + 3 * p + kk] * sWall[16 + p];
                    oa[k] = 0.70710678118654752f * u * g;
                } else if (k < 9) {
                    int kk = k - 4;
                    float g = fsig(0.5f * (z0.x * sWall[5] + z0.y * sWall[8] + z0.z * sWall[11] + z0.w * sWall[14]) + sBall[2]);
                    float u = 0.f;
#pragma unroll
                    for (int p = 0; p < 7; p++) u += Z[24 + 5 * p + kk] * sWall[22 + p];
                    oa[k] = 0.84515425472851657f * u * g;
                } else {
                    int kk = k - 9;
                    float g = fsig(0.5f * (z0.x * sWall[6] + z0.y * sWall[9] + z0.z * sWall[12] + z0.w * sWall[15]) + sBall[3]);
                    float u = 0.f;
#pragma unroll
                    for (int p = 0; p < 6; p++) u += Z[60 + 7 * p + kk] * sWall[29 + p];
                    oa[k] = 1.08012344973464367f * u * g;   // sqrt(7/6)
                }
            }
        } else {
            // role B: rows 4-8 (gated l=2)
#pragma unroll
            for (int el = 0; el < 2; el++) {
                const float* Z = sZ[pi & 1][el];
                float4 z0 = *(const float4*)Z;
                float g1 = fmaf(z0.x, rw[0], fmaf(z0.y, rw[1], fmaf(z0.z, rw[2], z0.w * rw[3])));
                g1 = fsig(0.5f * g1 + rw[4]);

                float q0, q1, q2, q3, q4;
                {
                    float4 v4;
                    v4 = *(const float4*)(Z + 24);
                    q0 = v4.x * rw[5]; q1 = v4.y * rw[5]; q2 = v4.z * rw[5]; q3 = v4.w * rw[5];
                    v4 = *(const float4*)(Z + 28);
                    q4 = v4.x * rw[5]; q0 = fmaf(v4.y, rw[6], q0); q1 = fmaf(v4.z, rw[6], q1); q2 = fmaf(v4.w, rw[6], q2);
                    v4 = *(const float4*)(Z + 32);
                    q3 = fmaf(v4.x, rw[6], q3); q4 = fmaf(v4.y, rw[6], q4); q0 = fmaf(v4.z, rw[7], q0); q1 = fmaf(v4.w, rw[7], q1);
                    v4 = *(const float4*)(Z + 36);
                    q2 = fmaf(v4.x, rw[7], q2); q3 = fmaf(v4.y, rw[7], q3); q4 = fmaf(v4.z, rw[7], q4); q0 = fmaf(v4.w, rw[8], q0);
                    v4 = *(const float4*)(Z + 40);
                    q1 = fmaf(v4.x, rw[8], q1); q2 = fmaf(v4.y, rw[8], q2); q3 = fmaf(v4.z, rw[8], q3); q4 = fmaf(v4.w, rw[8], q4);
                    v4 = *(const float4*)(Z + 44);
                    q0 = fmaf(v4.x, rw[9], q0); q1 = fmaf(v4.y, rw[9], q1); q2 = fmaf(v4.z, rw[9], q2); q3 = fmaf(v4.w, rw[9], q3);
                    v4 = *(const float4*)(Z + 48);
                    q4 = fmaf(v4.x, rw[9], q4); q0 = fmaf(v4.y, rw[10], q0); q1 = fmaf(v4.z, rw[10], q1); q2 = fmaf(v4.w, rw[10], q2);
                    v4 = *(const float4*)(Z + 52);
                    q3 = fmaf(v4.x, rw[10], q3); q4 = fmaf(v4.y, rw[10], q4); q0 = fmaf(v4.z, rw[11], q0); q1 = fmaf(v4.w, rw[11], q1);
                    v4 = *(const float4*)(Z + 56);   // Z[59] is padding (lane discarded)
                    q2 = fmaf(v4.x, rw[11], q2); q3 = fmaf(v4.y, rw[11], q3); q4 = fmaf(v4.z, rw[11], q4);
                }
                size_t base = ((size_t)(eb + el) * 9) * 128 + ch;
                float hh = S2 * g1;
                out[base + 512] = q0 * hh;
                out[base + 640] = q1 * hh;
                out[base + 768] = q2 * hh;
                out[base + 896] = q3 * hh;
                out[base + 1024] = q4 * hh;
            }
        }
        // no trailing barrier: ping-pong over pair parity + the per-pair barrier
        // give the needed ordering (reaching pair pi+2's phase-1 writes requires
        // passing pair pi+1's barrier, which is after all pair-pi phase-2 reads).
    }
}

extern "C" void kernel_launch(void* const* d_in, const int* in_sizes, int n_in,
                              void* d_out, int out_size) {
    const float* x    = (const float*)d_in[0];
    const float* y    = (const float*)d_in[1];
    const float* wcg  = (const float*)d_in[2];
    const float* bcg  = (const float*)d_in[3];
    const float* wall = (const float*)d_in[4];
    const float* ball = (const float*)d_in[5];
    float* out = (float*)d_out;

    cg_main_kernel<<<GRID, 256>>>(x, y, wcg, bcg, wall, ball, out);
}